// round 5
// baseline (speedup 1.0000x reference)
#include <cuda_runtime.h>
#include <cstdint>

#define BATCH 65536
#define RS 36   // permuted smem row stride in floats (32 data + 4 pad)

// ---------------- scratch (device globals; no allocation allowed) ----------
__device__ float g_h0[(size_t)BATCH * 1024];
__device__ float g_h1[(size_t)BATCH * 1024];
__device__ float g_h2[(size_t)BATCH * 512];
__device__ float g_s0[(size_t)BATCH * 256];
__device__ float g_s1[(size_t)BATCH * 128];
__device__ float g_w [(size_t)BATCH * 16];
__device__ float g_rb[(size_t)BATCH * 32];      // per-row fused bias: sum_e w*be2
__device__ float g_eh[(size_t)BATCH * 4096];    // w-scaled expert hidden [B, 16*256]
__device__ float g_part[(size_t)4 * BATCH * 32]; // final split-K partials

// ---------------- helpers ---------------------------------------------------
__device__ __forceinline__ float to_tf32(float x) {
    unsigned u;
    asm("cvt.rna.tf32.f32 %0, %1;" : "=r"(u) : "f"(x));
    return __uint_as_float(u);
}

__device__ __forceinline__ void mma_tf32(float* d, const float* a, const float* b) {
    asm volatile(
        "mma.sync.aligned.m16n8k8.row.col.f32.tf32.tf32.f32 "
        "{%0,%1,%2,%3}, {%4,%5,%6,%7}, {%8,%9}, {%0,%1,%2,%3};\n"
        : "+f"(d[0]), "+f"(d[1]), "+f"(d[2]), "+f"(d[3])
        : "r"(__float_as_uint(a[0])), "r"(__float_as_uint(a[1])),
          "r"(__float_as_uint(a[2])), "r"(__float_as_uint(a[3])),
          "r"(__float_as_uint(b[0])), "r"(__float_as_uint(b[1])));
}

// Permuted layout: element (q, k) of a 32-deep k-tile lives at
//   q*RS + (k&3)*8 + ((k>>2) ^ key)
// A key: ((q>>3)&1)  -> fragment reads: low row x=0, high row x=1 (compile-time)
// B key: ((q>>3)&3)  -> fragment reads: x = nf&3 (compile-time)

// ---------------- main GEMM: C = act(A[M,K] @ B[K,N] + bias) ----------------
// 128x128 block, 4 warps, 64x64 warp tiles, vectorized LDS.128 fragment loads.
// EXPERT: B is We1 [16, K, 256]; col n -> expert e=n>>8, h=n&255.
// SCALE:  multiply post-relu output by wsel[row*16 + e].
template<bool RELU, bool EXPERT, bool SCALE>
__global__ __launch_bounds__(128) void tc_gemm(
    const float* __restrict__ A, const float* __restrict__ B,
    const float* __restrict__ bias, const float* __restrict__ wsel,
    float* __restrict__ C, int K, int N)
{
    __shared__ __align__(16) float As[128 * RS];
    __shared__ __align__(16) float Bs[128 * RS];
    __shared__ float sbias[128];

    const int tid = threadIdx.x;
    const int warp = tid >> 5, lane = tid & 31;
    const int wm = warp >> 1, wn = warp & 1;        // 2x2 warp grid
    const int lg = lane >> 2, lt = lane & 3;
    const int m0 = blockIdx.y * 128;
    const int n0 = blockIdx.x * 128;

    const float* Bp; int ldb, bc0;
    if (EXPERT) {
        int e = n0 >> 8;
        Bp = B + (size_t)e * K * 256; ldb = 256; bc0 = n0 & 255;
    } else {
        Bp = B; ldb = N; bc0 = n0;
    }
    const int eidx = EXPERT ? (n0 >> 8) : 0;

    sbias[tid] = bias[n0 + tid];

    float acc[4][8][4];
#pragma unroll
    for (int i = 0; i < 4; i++)
#pragma unroll
        for (int j = 0; j < 8; j++)
#pragma unroll
            for (int k = 0; k < 4; k++) acc[i][j][k] = 0.f;

    for (int k0 = 0; k0 < K; k0 += 32) {
        __syncthreads();
        // ---- A tile: 128 rows x 32 k  (1024 float4, 8/thread) ----
#pragma unroll
        for (int j = 0; j < 8; j++) {
            int i = tid + j * 128;
            int r = i >> 3, kq = i & 7;
            float4 v = *(const float4*)(A + (size_t)(m0 + r) * K + k0 + kq * 4);
            int p = r * RS + (kq ^ ((r >> 3) & 1));
            As[p]      = to_tf32(v.x);
            As[p + 8]  = to_tf32(v.y);
            As[p + 16] = to_tf32(v.z);
            As[p + 24] = to_tf32(v.w);
        }
        // ---- B tile: 32 k-rows x 128 cols (1024 float4, 8/thread) ----
#pragma unroll
        for (int j = 0; j < 8; j++) {
            int i = tid + j * 128;
            int krow = i >> 5, c4 = (i & 31) << 2;
            float4 v = *(const float4*)(Bp + (size_t)(k0 + krow) * ldb + bc0 + c4);
            int p = c4 * RS + (krow & 3) * 8 + ((krow >> 2) ^ ((c4 >> 3) & 3));
            Bs[p]          = to_tf32(v.x);
            Bs[p + RS]     = to_tf32(v.y);
            Bs[p + 2 * RS] = to_tf32(v.z);
            Bs[p + 3 * RS] = to_tf32(v.w);
        }
        __syncthreads();

#pragma unroll
        for (int ks2 = 0; ks2 < 2; ks2++) {
            float a[4][8];
#pragma unroll
            for (int mf = 0; mf < 4; mf++) {
                int q = wm * 64 + mf * 16 + lg;
                float4 v0 = *(const float4*)&As[q * RS + lt * 8 + ks2 * 4];
                float4 v1 = *(const float4*)&As[(q + 8) * RS + lt * 8 + ks2 * 4];
                a[mf][0] = v0.x; a[mf][1] = v0.y; a[mf][2] = v0.z; a[mf][3] = v0.w;
                // high row stored with key=1: element p holds local k (p^1)
                a[mf][4] = v1.y; a[mf][5] = v1.x; a[mf][6] = v1.w; a[mf][7] = v1.z;
            }
            float b[8][4];
#pragma unroll
            for (int nf = 0; nf < 8; nf++) {
                int c = wn * 64 + nf * 8 + lg;
                float4 v = *(const float4*)&Bs[c * RS + lt * 8 + ks2 * 4];
                float vv[4] = { v.x, v.y, v.z, v.w };
                const int x = nf & 3;
                b[nf][0] = vv[0 ^ x]; b[nf][1] = vv[1 ^ x];
                b[nf][2] = vv[2 ^ x]; b[nf][3] = vv[3 ^ x];
            }
#pragma unroll
            for (int h = 0; h < 2; h++)
#pragma unroll
            for (int mf = 0; mf < 4; mf++) {
                float av[4] = { a[mf][2*h], a[mf][4 + 2*h], a[mf][2*h + 1], a[mf][5 + 2*h] };
#pragma unroll
                for (int nf = 0; nf < 8; nf++) {
                    float bv[2] = { b[nf][2*h], b[nf][2*h + 1] };
                    mma_tf32(acc[mf][nf], av, bv);
                }
            }
        }
    }

    // ---- epilogue: bias + relu (+ per-row expert weight) ----
#pragma unroll
    for (int mf = 0; mf < 4; mf++) {
        int row = m0 + wm * 64 + mf * 16 + lg;
        float ws0 = 1.f, ws1 = 1.f;
        if (SCALE) {
            ws0 = wsel[(size_t)row * 16 + eidx];
            ws1 = wsel[(size_t)(row + 8) * 16 + eidx];
        }
#pragma unroll
        for (int nf = 0; nf < 8; nf++) {
            int cl = wn * 64 + nf * 8 + lt * 2;
            int col = n0 + cl;
            float b0 = sbias[cl], b1 = sbias[cl + 1];
            float v0 = acc[mf][nf][0] + b0, v1 = acc[mf][nf][1] + b1;
            float v2 = acc[mf][nf][2] + b0, v3 = acc[mf][nf][3] + b1;
            if (RELU) {
                v0 = fmaxf(v0, 0.f); v1 = fmaxf(v1, 0.f);
                v2 = fmaxf(v2, 0.f); v3 = fmaxf(v3, 0.f);
            }
            if (SCALE) { v0 *= ws0; v1 *= ws0; v2 *= ws1; v3 *= ws1; }
            *(float2*)(C + (size_t)row * N + col)       = make_float2(v0, v1);
            *(float2*)(C + (size_t)(row + 8) * N + col) = make_float2(v2, v3);
        }
    }
}

// ---------------- selector logits + softmax + fused row bias ----------------
__global__ __launch_bounds__(256) void selector_kernel(
    const float* __restrict__ s1, const float* __restrict__ Ws2,
    const float* __restrict__ bs2, const float* __restrict__ be2,
    float* __restrict__ wout, float* __restrict__ rbout)
{
    __shared__ float Wsm[128 * 16];
    __shared__ float bsm[16];
    __shared__ float be2s[16 * 32];
    const int tid = threadIdx.x;
    for (int i = tid; i < 2048; i += 256) Wsm[i] = Ws2[i];
    for (int i = tid; i < 512; i += 256) be2s[i] = be2[i];
    if (tid < 16) bsm[tid] = bs2[tid];
    __syncthreads();

    const int warp = tid >> 5, lane = tid & 31;
    const int row = blockIdx.x * 8 + warp;

    float v[4];
#pragma unroll
    for (int j = 0; j < 4; j++) v[j] = s1[(size_t)row * 128 + j * 32 + lane];

    float mylog = -1e30f;
#pragma unroll
    for (int e = 0; e < 16; e++) {
        float p = 0.f;
#pragma unroll
        for (int j = 0; j < 4; j++) p += v[j] * Wsm[(j * 32 + lane) * 16 + e];
#pragma unroll
        for (int off = 16; off >= 1; off >>= 1)
            p += __shfl_xor_sync(0xffffffffu, p, off);
        if (lane == e) mylog = p + bsm[e];
    }
    float m = mylog;
#pragma unroll
    for (int off = 8; off >= 1; off >>= 1)
        m = fmaxf(m, __shfl_xor_sync(0xffffffffu, m, off, 16));
    float ex = __expf(mylog - m);
    float s = ex;
#pragma unroll
    for (int off = 8; off >= 1; off >>= 1)
        s += __shfl_xor_sync(0xffffffffu, s, off, 16);
    float wv = ex / s;
    if (lane < 16) wout[(size_t)row * 16 + lane] = wv;

    float rbv = 0.f;
#pragma unroll
    for (int e = 0; e < 16; e++) {
        float we = __shfl_sync(0xffffffffu, wv, e);
        rbv += we * be2s[e * 32 + lane];
    }
    rbout[(size_t)row * 32 + lane] = rbv;
}

// ---------------- final fused GEMM (split-K x4): part = g @ We2flat ---------
// grid (512, 4): 128-row blocks, each handles K-slice of 1024. 8 warps m16n32.
__global__ __launch_bounds__(256) void final_gemm(
    const float* __restrict__ g, const float* __restrict__ W2,
    float* __restrict__ part)
{
    __shared__ __align__(16) float As[128 * RS];
    __shared__ __align__(16) float Bs[32 * RS];

    const int tid = threadIdx.x;
    const int warp = tid >> 5, lane = tid & 31;
    const int lg = lane >> 2, lt = lane & 3;
    const int m0 = blockIdx.x * 128;
    const int kb = blockIdx.y * 1024;

    float acc[4][4];
#pragma unroll
    for (int nf = 0; nf < 4; nf++)
#pragma unroll
        for (int k = 0; k < 4; k++) acc[nf][k] = 0.f;

    for (int kt = 0; kt < 32; kt++) {
        const int k0 = kb + kt * 32;
        __syncthreads();
#pragma unroll
        for (int j = 0; j < 4; j++) {
            int i = tid + j * 256;
            int r = i >> 3, kq = i & 7;
            float4 v = *(const float4*)(g + (size_t)(m0 + r) * 4096 + k0 + kq * 4);
            int p = r * RS + (kq ^ ((r >> 3) & 1));
            As[p]      = to_tf32(v.x);
            As[p + 8]  = to_tf32(v.y);
            As[p + 16] = to_tf32(v.z);
            As[p + 24] = to_tf32(v.w);
        }
        {   // B: 32 k-rows x 32 cols = 256 float4, 1/thread
            int krow = tid >> 3, c4 = (tid & 7) << 2;
            float4 v = *(const float4*)(W2 + (size_t)(k0 + krow) * 32 + c4);
            int p = c4 * RS + (krow & 3) * 8 + ((krow >> 2) ^ ((c4 >> 3) & 3));
            Bs[p]          = to_tf32(v.x);
            Bs[p + RS]     = to_tf32(v.y);
            Bs[p + 2 * RS] = to_tf32(v.z);
            Bs[p + 3 * RS] = to_tf32(v.w);
        }
        __syncthreads();

#pragma unroll
        for (int ks2 = 0; ks2 < 2; ks2++) {
            int q = warp * 16 + lg;
            float4 v0 = *(const float4*)&As[q * RS + lt * 8 + ks2 * 4];
            float4 v1 = *(const float4*)&As[(q + 8) * RS + lt * 8 + ks2 * 4];
            float a[8];
            a[0] = v0.x; a[1] = v0.y; a[2] = v0.z; a[3] = v0.w;
            a[4] = v1.y; a[5] = v1.x; a[6] = v1.w; a[7] = v1.z;
            float b[4][4];
#pragma unroll
            for (int nf = 0; nf < 4; nf++) {
                int c = nf * 8 + lg;
                float4 v = *(const float4*)&Bs[c * RS + lt * 8 + ks2 * 4];
                float vv[4] = { v.x, v.y, v.z, v.w };
                const int x = nf & 3;
                b[nf][0] = vv[0 ^ x]; b[nf][1] = vv[1 ^ x];
                b[nf][2] = vv[2 ^ x]; b[nf][3] = vv[3 ^ x];
            }
#pragma unroll
            for (int h = 0; h < 2; h++) {
                float av[4] = { a[2*h], a[4 + 2*h], a[2*h + 1], a[5 + 2*h] };
#pragma unroll
                for (int nf = 0; nf < 4; nf++) {
                    float bv[2] = { b[nf][2*h], b[nf][2*h + 1] };
                    mma_tf32(acc[nf], av, bv);
                }
            }
        }
    }

    float* P = part + (size_t)blockIdx.y * ((size_t)BATCH * 32);
    int row = m0 + warp * 16 + lg;
#pragma unroll
    for (int nf = 0; nf < 4; nf++) {
        int col = nf * 8 + lt * 2;
        *(float2*)(P + (size_t)row * 32 + col)       = make_float2(acc[nf][0], acc[nf][1]);
        *(float2*)(P + (size_t)(row + 8) * 32 + col) = make_float2(acc[nf][2], acc[nf][3]);
    }
}

// ---------------- split-K reduce + row-bias add -----------------------------
__global__ __launch_bounds__(256) void reduce_final(
    const float* __restrict__ part, const float* __restrict__ rb,
    float* __restrict__ out)
{
    size_t idx = (size_t)blockIdx.x * 256 + threadIdx.x;   // float4 units
    const size_t S = (size_t)BATCH * 32 / 4;
    const float4* p4 = (const float4*)part;
    float4 r = ((const float4*)rb)[idx];
#pragma unroll
    for (int s = 0; s < 4; s++) {
        float4 p = p4[s * S + idx];
        r.x += p.x; r.y += p.y; r.z += p.z; r.w += p.w;
    }
    ((float4*)out)[idx] = r;
}

// ---------------- launch -----------------------------------------------------
extern "C" void kernel_launch(void* const* d_in, const int* in_sizes, int n_in,
                              void* d_out, int out_size)
{
    const float* obs = (const float*)d_in[0];
    const float* Wb0 = (const float*)d_in[1];  const float* bb0 = (const float*)d_in[2];
    const float* Wb1 = (const float*)d_in[3];  const float* bb1 = (const float*)d_in[4];
    const float* Wb2 = (const float*)d_in[5];  const float* bb2 = (const float*)d_in[6];
    const float* We1 = (const float*)d_in[7];  const float* be1 = (const float*)d_in[8];
    const float* We2 = (const float*)d_in[9];  const float* be2 = (const float*)d_in[10];
    const float* Ws0 = (const float*)d_in[11]; const float* bs0 = (const float*)d_in[12];
    const float* Ws1 = (const float*)d_in[13]; const float* bs1 = (const float*)d_in[14];
    const float* Ws2 = (const float*)d_in[15]; const float* bs2 = (const float*)d_in[16];
    float* out = (float*)d_out;

    float *h0, *h1, *h2, *s0, *s1, *w, *rb, *eh, *part;
    cudaGetSymbolAddress((void**)&h0, g_h0);
    cudaGetSymbolAddress((void**)&h1, g_h1);
    cudaGetSymbolAddress((void**)&h2, g_h2);
    cudaGetSymbolAddress((void**)&s0, g_s0);
    cudaGetSymbolAddress((void**)&s1, g_s1);
    cudaGetSymbolAddress((void**)&w,  g_w);
    cudaGetSymbolAddress((void**)&rb, g_rb);
    cudaGetSymbolAddress((void**)&eh, g_eh);
    cudaGetSymbolAddress((void**)&part, g_part);

    const int MB = BATCH / 128;   // 512

    // selector chain first (w needed by experts-L1 epilogue)
    tc_gemm<true, false, false><<<dim3(2, MB), 128>>>(obs, Ws0, bs0, nullptr, s0, 512, 256);
    tc_gemm<true, false, false><<<dim3(1, MB), 128>>>(s0, Ws1, bs1, nullptr, s1, 256, 128);
    selector_kernel<<<BATCH / 8, 256>>>(s1, Ws2, bs2, be2, w, rb);

    // backbone
    tc_gemm<true, false, false><<<dim3(8, MB), 128>>>(obs, Wb0, bb0, nullptr, h0, 512, 1024);
    tc_gemm<true, false, false><<<dim3(8, MB), 128>>>(h0, Wb1, bb1, nullptr, h1, 1024, 1024);
    tc_gemm<true, false, false><<<dim3(4, MB), 128>>>(h1, Wb2, bb2, nullptr, h2, 1024, 512);

    // experts layer 1, w folded into epilogue: g = relu(h2 @ We1 + be1) * w
    tc_gemm<true, true, true><<<dim3(32, MB), 128>>>(h2, We1, be1, w, eh, 512, 4096);

    // fusion: out = g @ We2flat + rb  (split-K x4 + reduce)
    final_gemm<<<dim3(MB, 4), 256>>>(eh, We2, part);
    reduce_final<<<(BATCH * 32 / 4) / 256, 256>>>(part, rb, out);
}

// round 6
// speedup vs baseline: 1.8812x; 1.8812x over previous
#include <cuda_runtime.h>
#include <cuda_fp16.h>
#include <cstdint>

#define BATCH 65536

// ---------------- scratch (device globals; no allocation allowed) ----------
__device__ __half g_h0[(size_t)BATCH * 1024];
__device__ __half g_h1[(size_t)BATCH * 1024];
__device__ __half g_h2[(size_t)BATCH * 512];
__device__ __half g_s0[(size_t)BATCH * 256];
__device__ __half g_s1[(size_t)BATCH * 128];
__device__ float  g_w [(size_t)BATCH * 16];
__device__ float  g_rb[(size_t)BATCH * 32];       // per-row fused bias: sum_e w*be2
__device__ __half g_eh[(size_t)BATCH * 4096];     // w-scaled expert hidden [B,16*256]
__device__ float  g_part[(size_t)4 * BATCH * 32]; // final split-K partials

// ---------------- helpers ---------------------------------------------------
__device__ __forceinline__ uint32_t smem_u32(const void* p) {
    uint32_t a;
    asm("{ .reg .u64 t; cvta.to.shared.u64 t, %1; cvt.u32.u64 %0, t; }" : "=r"(a) : "l"(p));
    return a;
}

__device__ __forceinline__ void mma_f16(float* d, const uint32_t* a, uint32_t b0, uint32_t b1) {
    asm volatile(
        "mma.sync.aligned.m16n8k16.row.col.f32.f16.f16.f32 "
        "{%0,%1,%2,%3}, {%4,%5,%6,%7}, {%8,%9}, {%0,%1,%2,%3};\n"
        : "+f"(d[0]), "+f"(d[1]), "+f"(d[2]), "+f"(d[3])
        : "r"(a[0]), "r"(a[1]), "r"(a[2]), "r"(a[3]), "r"(b0), "r"(b1));
}

#define LDSM_X4(r, addr) \
    asm volatile("ldmatrix.sync.aligned.m8n8.x4.shared.b16 {%0,%1,%2,%3}, [%4];" \
        : "=r"((r)[0]), "=r"((r)[1]), "=r"((r)[2]), "=r"((r)[3]) : "r"(addr))
#define LDSM_X4_T(r, addr) \
    asm volatile("ldmatrix.sync.aligned.m8n8.x4.trans.shared.b16 {%0,%1,%2,%3}, [%4];" \
        : "=r"((r)[0]), "=r"((r)[1]), "=r"((r)[2]), "=r"((r)[3]) : "r"(addr))

__device__ __forceinline__ uint32_t packh2(float lo, float hi) {
    __half2 h = __floats2half2_rn(lo, hi);
    return *(uint32_t*)&h;
}

// smem strides (bytes)
#define RSA 80     // A row: 32 halfs (64B) + 16B pad
#define RSB 272    // B row: 128 halfs (256B) + 16B pad

// ---------------- main GEMM: C(half) = act(A[M,K] @ B[K,N] + bias) ----------
// 128x128 block, 256 thr, 8 warps (2x4), warp tile 64x32, m16n8k16 f16 MMA.
// A either fp32 (AFLOAT) or half; B fp32 weights (cvt on load).
// EXPERT: B = We1 [16,K,256], col n -> expert n>>8. SCALE: multiply by wsel.
template<bool RELU, bool EXPERT, bool SCALE, bool AFLOAT>
__global__ __launch_bounds__(256) void tc_gemm(
    const void* __restrict__ Ain, const float* __restrict__ B,
    const float* __restrict__ bias, const float* __restrict__ wsel,
    __half* __restrict__ C, int K, int N)
{
    __shared__ __align__(16) char AsB[128 * RSA];
    __shared__ __align__(16) char BsB[32 * RSB];
    __shared__ float sbias[128];

    const int tid = threadIdx.x;
    const int warp = tid >> 5, lane = tid & 31;
    const int rA = (warp >> 2) * 64, cB = (warp & 3) * 32;
    const int lg = lane >> 2, lt = lane & 3;
    const int m0 = blockIdx.y * 128;
    const int n0 = blockIdx.x * 128;

    const float* Bp; int ldb, bc0;
    if (EXPERT) { Bp = B + (size_t)(n0 >> 8) * K * 256; ldb = 256; bc0 = n0 & 255; }
    else        { Bp = B; ldb = N; bc0 = n0; }
    const int eidx = EXPERT ? (n0 >> 8) : 0;

    if (tid < 128) sbias[tid] = bias[n0 + tid];

    const uint32_t As = smem_u32(AsB), Bs = smem_u32(BsB);
    // ldmatrix lane addressing
    const int li = lane & 7, ls = lane >> 3;
    const uint32_t aAddr = As + (uint32_t)(rA + li + 8 * (ls & 1)) * RSA + (ls >> 1) * 16;
    const uint32_t bAddr = Bs + (uint32_t)(li + 8 * (ls & 1)) * RSB + (uint32_t)(cB + 8 * (ls >> 1)) * 2;

    float acc[4][4][4];
#pragma unroll
    for (int i = 0; i < 4; i++)
#pragma unroll
        for (int j = 0; j < 4; j++)
#pragma unroll
            for (int k = 0; k < 4; k++) acc[i][j][k] = 0.f;

    for (int k0 = 0; k0 < K; k0 += 32) {
        __syncthreads();
        // ---- A tile: 128 rows x 32 halfs ----
#pragma unroll
        for (int j = 0; j < 2; j++) {
            int idx = tid + 256 * j;
            int r = idx >> 2, q = idx & 3;
            uint4 u;
            if (AFLOAT) {
                const float* src = (const float*)Ain + (size_t)(m0 + r) * K + k0 + q * 8;
                float4 v0 = *(const float4*)src;
                float4 v1 = *(const float4*)(src + 4);
                u.x = packh2(v0.x, v0.y); u.y = packh2(v0.z, v0.w);
                u.z = packh2(v1.x, v1.y); u.w = packh2(v1.z, v1.w);
            } else {
                u = *(const uint4*)((const __half*)Ain + (size_t)(m0 + r) * K + k0 + q * 8);
            }
            *(uint4*)(AsB + r * RSA + q * 16) = u;
        }
        // ---- B tile: 32 k-rows x 128 cols (fp32 -> half) ----
#pragma unroll
        for (int j = 0; j < 2; j++) {
            int idx = tid + 256 * j;
            int krow = idx >> 4, n8 = idx & 15;
            const float* src = Bp + (size_t)(k0 + krow) * ldb + bc0 + n8 * 8;
            float4 v0 = *(const float4*)src;
            float4 v1 = *(const float4*)(src + 4);
            uint4 u;
            u.x = packh2(v0.x, v0.y); u.y = packh2(v0.z, v0.w);
            u.z = packh2(v1.x, v1.y); u.w = packh2(v1.z, v1.w);
            *(uint4*)(BsB + krow * RSB + n8 * 16) = u;
        }
        __syncthreads();

#pragma unroll
        for (int h = 0; h < 2; h++) {
            uint32_t a[4][4];
#pragma unroll
            for (int mf = 0; mf < 4; mf++)
                LDSM_X4(a[mf], aAddr + mf * (16 * RSA) + h * 32);
            uint32_t b[2][4];
#pragma unroll
            for (int nfp = 0; nfp < 2; nfp++)
                LDSM_X4_T(b[nfp], bAddr + nfp * 32 + h * (16 * RSB));
#pragma unroll
            for (int mf = 0; mf < 4; mf++)
#pragma unroll
                for (int nf = 0; nf < 4; nf++)
                    mma_f16(acc[mf][nf], a[mf], b[nf >> 1][(nf & 1) * 2], b[nf >> 1][(nf & 1) * 2 + 1]);
        }
    }

    // ---- epilogue: bias + relu (+ expert weight), store half ----
#pragma unroll
    for (int mf = 0; mf < 4; mf++) {
        int row = m0 + rA + mf * 16 + lg;
        float ws0 = 1.f, ws1 = 1.f;
        if (SCALE) {
            ws0 = wsel[(size_t)row * 16 + eidx];
            ws1 = wsel[(size_t)(row + 8) * 16 + eidx];
        }
#pragma unroll
        for (int nf = 0; nf < 4; nf++) {
            int cl = cB + nf * 8 + lt * 2;
            int col = n0 + cl;
            float b0 = sbias[cl], b1 = sbias[cl + 1];
            float v0 = acc[mf][nf][0] + b0, v1 = acc[mf][nf][1] + b1;
            float v2 = acc[mf][nf][2] + b0, v3 = acc[mf][nf][3] + b1;
            if (RELU) {
                v0 = fmaxf(v0, 0.f); v1 = fmaxf(v1, 0.f);
                v2 = fmaxf(v2, 0.f); v3 = fmaxf(v3, 0.f);
            }
            if (SCALE) { v0 *= ws0; v1 *= ws0; v2 *= ws1; v3 *= ws1; }
            *(uint32_t*)(C + (size_t)row * N + col)       = packh2(v0, v1);
            *(uint32_t*)(C + (size_t)(row + 8) * N + col) = packh2(v2, v3);
        }
    }
}

// ---------------- selector logits + softmax + fused row bias ----------------
__global__ __launch_bounds__(256) void selector_kernel(
    const __half* __restrict__ s1, const float* __restrict__ Ws2,
    const float* __restrict__ bs2, const float* __restrict__ be2,
    float* __restrict__ wout, float* __restrict__ rbout)
{
    __shared__ float Wsm[128 * 16];
    __shared__ float bsm[16];
    __shared__ float be2s[16 * 32];
    const int tid = threadIdx.x;
    for (int i = tid; i < 2048; i += 256) Wsm[i] = Ws2[i];
    for (int i = tid; i < 512; i += 256) be2s[i] = be2[i];
    if (tid < 16) bsm[tid] = bs2[tid];
    __syncthreads();

    const int warp = tid >> 5, lane = tid & 31;
    const int row = blockIdx.x * 8 + warp;

    float v[4];
#pragma unroll
    for (int j = 0; j < 4; j++)
        v[j] = __half2float(s1[(size_t)row * 128 + j * 32 + lane]);

    float mylog = -1e30f;
#pragma unroll
    for (int e = 0; e < 16; e++) {
        float p = 0.f;
#pragma unroll
        for (int j = 0; j < 4; j++) p += v[j] * Wsm[(j * 32 + lane) * 16 + e];
#pragma unroll
        for (int off = 16; off >= 1; off >>= 1)
            p += __shfl_xor_sync(0xffffffffu, p, off);
        if (lane == e) mylog = p + bsm[e];
    }
    float m = mylog;
#pragma unroll
    for (int off = 8; off >= 1; off >>= 1)
        m = fmaxf(m, __shfl_xor_sync(0xffffffffu, m, off, 16));
    float ex = __expf(mylog - m);
    float s = ex;
#pragma unroll
    for (int off = 8; off >= 1; off >>= 1)
        s += __shfl_xor_sync(0xffffffffu, s, off, 16);
    float wv = ex / s;
    if (lane < 16) wout[(size_t)row * 16 + lane] = wv;

    float rbv = 0.f;
#pragma unroll
    for (int e = 0; e < 16; e++) {
        float we = __shfl_sync(0xffffffffu, wv, e);
        rbv += we * be2s[e * 32 + lane];
    }
    rbout[(size_t)row * 32 + lane] = rbv;
}

// ---------------- final fused GEMM (split-K x4): part = g @ We2flat ---------
// g half [B,4096]; grid (512,4); 8 warps, warp tile 16x32.
__global__ __launch_bounds__(256) void final_gemm(
    const __half* __restrict__ g, const float* __restrict__ W2,
    float* __restrict__ part)
{
    __shared__ __align__(16) char AsB[128 * RSA];
    __shared__ __align__(16) char BsB[32 * RSA];   // 32 rows x 32 halfs, stride 80B

    const int tid = threadIdx.x;
    const int warp = tid >> 5, lane = tid & 31;
    const int lg = lane >> 2, lt = lane & 3;
    const int m0 = blockIdx.x * 128;
    const int kb = blockIdx.y * 1024;

    const uint32_t As = smem_u32(AsB), Bs = smem_u32(BsB);
    const int li = lane & 7, ls = lane >> 3;
    const uint32_t aAddr = As + (uint32_t)(warp * 16 + li + 8 * (ls & 1)) * RSA + (ls >> 1) * 16;
    const uint32_t bAddr = Bs + (uint32_t)(li + 8 * (ls & 1)) * RSA + (uint32_t)(8 * (ls >> 1)) * 2;

    float acc[4][4];
#pragma unroll
    for (int nf = 0; nf < 4; nf++)
#pragma unroll
        for (int k = 0; k < 4; k++) acc[nf][k] = 0.f;

    for (int kt = 0; kt < 32; kt++) {
        const int k0 = kb + kt * 32;
        __syncthreads();
#pragma unroll
        for (int j = 0; j < 2; j++) {
            int idx = tid + 256 * j;
            int r = idx >> 2, q = idx & 3;
            uint4 u = *(const uint4*)(g + (size_t)(m0 + r) * 4096 + k0 + q * 8);
            *(uint4*)(AsB + r * RSA + q * 16) = u;
        }
        if (tid < 128) {
            int krow = tid >> 2, q = tid & 3;
            const float* src = W2 + (size_t)(k0 + krow) * 32 + q * 8;
            float4 v0 = *(const float4*)src;
            float4 v1 = *(const float4*)(src + 4);
            uint4 u;
            u.x = packh2(v0.x, v0.y); u.y = packh2(v0.z, v0.w);
            u.z = packh2(v1.x, v1.y); u.w = packh2(v1.z, v1.w);
            *(uint4*)(BsB + krow * RSA + q * 16) = u;
        }
        __syncthreads();

#pragma unroll
        for (int h = 0; h < 2; h++) {
            uint32_t a[4];
            LDSM_X4(a, aAddr + h * 32);
            uint32_t b[2][4];
#pragma unroll
            for (int nfp = 0; nfp < 2; nfp++)
                LDSM_X4_T(b[nfp], bAddr + nfp * 32 + h * (16 * RSA));
#pragma unroll
            for (int nf = 0; nf < 4; nf++)
                mma_f16(acc[nf], a, b[nf >> 1][(nf & 1) * 2], b[nf >> 1][(nf & 1) * 2 + 1]);
        }
    }

    float* P = part + (size_t)blockIdx.y * ((size_t)BATCH * 32);
    int row = m0 + warp * 16 + lg;
#pragma unroll
    for (int nf = 0; nf < 4; nf++) {
        int col = nf * 8 + lt * 2;
        *(float2*)(P + (size_t)row * 32 + col)       = make_float2(acc[nf][0], acc[nf][1]);
        *(float2*)(P + (size_t)(row + 8) * 32 + col) = make_float2(acc[nf][2], acc[nf][3]);
    }
}

// ---------------- split-K reduce + row-bias add -----------------------------
__global__ __launch_bounds__(256) void reduce_final(
    const float* __restrict__ part, const float* __restrict__ rb,
    float* __restrict__ out)
{
    size_t idx = (size_t)blockIdx.x * 256 + threadIdx.x;   // float4 units
    const size_t S = (size_t)BATCH * 32 / 4;
    const float4* p4 = (const float4*)part;
    float4 r = ((const float4*)rb)[idx];
#pragma unroll
    for (int s = 0; s < 4; s++) {
        float4 p = p4[s * S + idx];
        r.x += p.x; r.y += p.y; r.z += p.z; r.w += p.w;
    }
    ((float4*)out)[idx] = r;
}

// ---------------- launch -----------------------------------------------------
extern "C" void kernel_launch(void* const* d_in, const int* in_sizes, int n_in,
                              void* d_out, int out_size)
{
    const float* obs = (const float*)d_in[0];
    const float* Wb0 = (const float*)d_in[1];  const float* bb0 = (const float*)d_in[2];
    const float* Wb1 = (const float*)d_in[3];  const float* bb1 = (const float*)d_in[4];
    const float* Wb2 = (const float*)d_in[5];  const float* bb2 = (const float*)d_in[6];
    const float* We1 = (const float*)d_in[7];  const float* be1 = (const float*)d_in[8];
    const float* We2 = (const float*)d_in[9];  const float* be2 = (const float*)d_in[10];
    const float* Ws0 = (const float*)d_in[11]; const float* bs0 = (const float*)d_in[12];
    const float* Ws1 = (const float*)d_in[13]; const float* bs1 = (const float*)d_in[14];
    const float* Ws2 = (const float*)d_in[15]; const float* bs2 = (const float*)d_in[16];
    float* out = (float*)d_out;

    __half *h0, *h1, *h2, *s0, *s1, *eh;
    float *w, *rb, *part;
    cudaGetSymbolAddress((void**)&h0, g_h0);
    cudaGetSymbolAddress((void**)&h1, g_h1);
    cudaGetSymbolAddress((void**)&h2, g_h2);
    cudaGetSymbolAddress((void**)&s0, g_s0);
    cudaGetSymbolAddress((void**)&s1, g_s1);
    cudaGetSymbolAddress((void**)&w,  g_w);
    cudaGetSymbolAddress((void**)&rb, g_rb);
    cudaGetSymbolAddress((void**)&eh, g_eh);
    cudaGetSymbolAddress((void**)&part, g_part);

    const int MB = BATCH / 128;   // 512

    // selector chain first (w needed by experts-L1 epilogue)
    tc_gemm<true, false, false, true ><<<dim3(2, MB), 256>>>(obs, Ws0, bs0, nullptr, s0, 512, 256);
    tc_gemm<true, false, false, false><<<dim3(1, MB), 256>>>(s0, Ws1, bs1, nullptr, s1, 256, 128);
    selector_kernel<<<BATCH / 8, 256>>>(s1, Ws2, bs2, be2, w, rb);

    // backbone
    tc_gemm<true, false, false, true ><<<dim3(8, MB), 256>>>(obs, Wb0, bb0, nullptr, h0, 512, 1024);
    tc_gemm<true, false, false, false><<<dim3(8, MB), 256>>>(h0, Wb1, bb1, nullptr, h1, 1024, 1024);
    tc_gemm<true, false, false, false><<<dim3(4, MB), 256>>>(h1, Wb2, bb2, nullptr, h2, 1024, 512);

    // experts layer 1, w folded into epilogue: g = relu(h2 @ We1 + be1) * w
    tc_gemm<true, true, true, false><<<dim3(32, MB), 256>>>(h2, We1, be1, w, eh, 512, 4096);

    // fusion: out = g @ We2flat + rb  (split-K x4 + reduce)
    final_gemm<<<dim3(MB, 4), 256>>>(eh, We2, part);
    reduce_final<<<(BATCH * 32 / 4) / 256, 256>>>(part, rb, out);
}

// round 7
// speedup vs baseline: 2.2809x; 1.2125x over previous
#include <cuda_runtime.h>
#include <cuda_fp16.h>
#include <cstdint>

#define BATCH 65536
#define RSA 80     // A smem row: 32 halfs (64B) + 16B pad

// ---------------- scratch (device globals; no allocation allowed) ----------
__device__ __half g_obsh[(size_t)BATCH * 512];
__device__ __half g_h0[(size_t)BATCH * 1024];
__device__ __half g_h1[(size_t)BATCH * 1024];
__device__ __half g_h2[(size_t)BATCH * 512];
__device__ __half g_s0[(size_t)BATCH * 256];
__device__ __half g_s1[(size_t)BATCH * 128];
__device__ float  g_w [(size_t)BATCH * 16];
__device__ float  g_rb[(size_t)BATCH * 32];
__device__ __half g_eh[(size_t)BATCH * 4096];
__device__ float  g_part[(size_t)4 * BATCH * 32];
// fp16 weights (converted once per replay; deterministic)
__device__ __half g_Wb0h[512 * 1024];
__device__ __half g_Wb1h[1024 * 1024];
__device__ __half g_Wb2h[1024 * 512];
__device__ __half g_Ws0h[512 * 256];
__device__ __half g_Ws1h[256 * 128];
__device__ __half g_We1h[16 * 512 * 256];
__device__ __half g_We2h[4096 * 32];

// ---------------- helpers ---------------------------------------------------
__device__ __forceinline__ uint32_t smem_u32(const void* p) {
    uint32_t a;
    asm("{ .reg .u64 t; cvta.to.shared.u64 t, %1; cvt.u32.u64 %0, t; }" : "=r"(a) : "l"(p));
    return a;
}
__device__ __forceinline__ void mma_f16(float* d, const uint32_t* a, uint32_t b0, uint32_t b1) {
    asm volatile(
        "mma.sync.aligned.m16n8k16.row.col.f32.f16.f16.f32 "
        "{%0,%1,%2,%3}, {%4,%5,%6,%7}, {%8,%9}, {%0,%1,%2,%3};\n"
        : "+f"(d[0]), "+f"(d[1]), "+f"(d[2]), "+f"(d[3])
        : "r"(a[0]), "r"(a[1]), "r"(a[2]), "r"(a[3]), "r"(b0), "r"(b1));
}
#define LDSM_X4(r, addr) \
    asm volatile("ldmatrix.sync.aligned.m8n8.x4.shared.b16 {%0,%1,%2,%3}, [%4];" \
        : "=r"((r)[0]), "=r"((r)[1]), "=r"((r)[2]), "=r"((r)[3]) : "r"(addr))
#define LDSM_X4_T(r, addr) \
    asm volatile("ldmatrix.sync.aligned.m8n8.x4.trans.shared.b16 {%0,%1,%2,%3}, [%4];" \
        : "=r"((r)[0]), "=r"((r)[1]), "=r"((r)[2]), "=r"((r)[3]) : "r"(addr))
#define CP_ASYNC16(dst, src) \
    asm volatile("cp.async.cg.shared.global [%0], [%1], 16;\n" :: "r"(dst), "l"(src))
#define CP_COMMIT() asm volatile("cp.async.commit_group;\n" ::: "memory")
#define CP_WAIT0()  asm volatile("cp.async.wait_group 0;\n" ::: "memory")

__device__ __forceinline__ uint32_t packh2(float lo, float hi) {
    __half2 h = __floats2half2_rn(lo, hi);
    return *(uint32_t*)&h;
}

// ---------------- fp32 -> fp16 conversion (8 elems/thread) ------------------
__global__ __launch_bounds__(256) void f2h_kernel(
    const float* __restrict__ src, __half* __restrict__ dst, size_t n8)
{
    size_t i = (size_t)blockIdx.x * 256 + threadIdx.x;
    if (i >= n8) return;
    float4 a = ((const float4*)src)[2 * i];
    float4 b = ((const float4*)src)[2 * i + 1];
    uint4 u;
    u.x = packh2(a.x, a.y); u.y = packh2(a.z, a.w);
    u.z = packh2(b.x, b.y); u.w = packh2(b.z, b.w);
    ((uint4*)dst)[i] = u;
}

// ---------------- main GEMM: C(half) = act(A[M,K] @ B[K,N] + bias) ----------
// 128 x BN block, 256 thr, 8 warps (2 x 4), warp tile 64 x (BN/4).
// fp16 A and B, cp.async double-buffered, ldmatrix fragments.
// EXPERT (BN=256): B = We1h flat [16,K,256]; x-block == expert. SCALE: *wsel.
template<int BN, bool RELU, bool EXPERT, bool SCALE>
__global__ __launch_bounds__(256, 1) void tc_gemm(
    const __half* __restrict__ A, const __half* __restrict__ B,
    const float* __restrict__ bias, const float* __restrict__ wsel,
    __half* __restrict__ C, int K, int N)
{
    extern __shared__ char smem[];
    constexpr int RSB = BN * 2 + 16;
    constexpr int ASZ = 128 * RSA;
    constexpr int STG = ASZ + 32 * RSB;
    constexpr int CPR = BN / 8;         // 16B chunks per B row
    constexpr int NF  = BN / 32;        // n-fragments (8-wide) per warp
    float* sbias = (float*)(smem + 2 * STG);

    const int tid = threadIdx.x, warp = tid >> 5, lane = tid & 31;
    const int rA = (warp >> 2) * 64, cB = (warp & 3) * (BN / 4);
    const int lg = lane >> 2, lt = lane & 3;
    const int m0 = blockIdx.y * 128, n0 = blockIdx.x * BN;

    const __half* Bp; int ldb;
    if (EXPERT) { Bp = B + (size_t)(n0 >> 8) * K * 256; ldb = 256; }
    else        { Bp = B + n0; ldb = N; }
    const int eidx = EXPERT ? (n0 >> 8) : 0;

    for (int i = tid; i < BN; i += 256) sbias[i] = bias[n0 + i];

    const uint32_t smb = smem_u32(smem);
    const int li = lane & 7, ls = lane >> 3;
    const uint32_t aOff = (uint32_t)(rA + li + 8 * (ls & 1)) * RSA + (ls >> 1) * 16;
    const uint32_t bOff = ASZ + (uint32_t)(li + 8 * (ls & 1)) * RSB
                        + (uint32_t)(cB + 8 * (ls >> 1)) * 2;

    float acc[4][NF][4];
#pragma unroll
    for (int i = 0; i < 4; i++)
#pragma unroll
        for (int j = 0; j < NF; j++)
#pragma unroll
            for (int k = 0; k < 4; k++) acc[i][j][k] = 0.f;

    const int NT = K >> 5;

#define LOAD_STAGE(t)                                                          \
    {                                                                          \
        const uint32_t base = smb + ((t) & 1) * STG;                           \
        const int k0 = (t) * 32;                                               \
        _Pragma("unroll")                                                      \
        for (int j = 0; j < 2; j++) {                                          \
            int i = tid + 256 * j;                                             \
            int r = i >> 2, q = i & 3;                                         \
            CP_ASYNC16(base + r * RSA + q * 16,                                \
                       A + (size_t)(m0 + r) * K + k0 + q * 8);                 \
        }                                                                      \
        _Pragma("unroll")                                                      \
        for (int j = 0; j < BN / 64; j++) {                                    \
            int i = tid + 256 * j;                                             \
            int krow = i / CPR, c16 = i % CPR;                                 \
            CP_ASYNC16(base + ASZ + krow * RSB + c16 * 16,                     \
                       Bp + (size_t)(k0 + krow) * ldb + c16 * 8);              \
        }                                                                      \
        CP_COMMIT();                                                           \
    }

    LOAD_STAGE(0);

    for (int t = 0; t < NT; t++) {
        CP_WAIT0();
        __syncthreads();
        if (t + 1 < NT) LOAD_STAGE(t + 1);

        const uint32_t base = smb + (t & 1) * STG;
#pragma unroll
        for (int h = 0; h < 2; h++) {
            uint32_t a[4][4];
#pragma unroll
            for (int mf = 0; mf < 4; mf++)
                LDSM_X4(a[mf], base + aOff + mf * (16 * RSA) + h * 32);
            uint32_t b[NF / 2][4];
#pragma unroll
            for (int nfp = 0; nfp < NF / 2; nfp++)
                LDSM_X4_T(b[nfp], base + bOff + nfp * 32 + h * (16 * RSB));
#pragma unroll
            for (int mf = 0; mf < 4; mf++)
#pragma unroll
                for (int nf = 0; nf < NF; nf++)
                    mma_f16(acc[mf][nf], a[mf],
                            b[nf >> 1][(nf & 1) * 2], b[nf >> 1][(nf & 1) * 2 + 1]);
        }
        __syncthreads();
    }
#undef LOAD_STAGE

    // ---- epilogue ----
#pragma unroll
    for (int mf = 0; mf < 4; mf++) {
        int row = m0 + rA + mf * 16 + lg;
        float ws0 = 1.f, ws1 = 1.f;
        if (SCALE) {
            ws0 = wsel[(size_t)row * 16 + eidx];
            ws1 = wsel[(size_t)(row + 8) * 16 + eidx];
        }
#pragma unroll
        for (int nf = 0; nf < NF; nf++) {
            int cl = cB + nf * 8 + lt * 2;
            int col = n0 + cl;
            float b0 = sbias[cl], b1 = sbias[cl + 1];
            float v0 = acc[mf][nf][0] + b0, v1 = acc[mf][nf][1] + b1;
            float v2 = acc[mf][nf][2] + b0, v3 = acc[mf][nf][3] + b1;
            if (RELU) {
                v0 = fmaxf(v0, 0.f); v1 = fmaxf(v1, 0.f);
                v2 = fmaxf(v2, 0.f); v3 = fmaxf(v3, 0.f);
            }
            if (SCALE) { v0 *= ws0; v1 *= ws0; v2 *= ws1; v3 *= ws1; }
            *(uint32_t*)(C + (size_t)row * N + col)       = packh2(v0, v1);
            *(uint32_t*)(C + (size_t)(row + 8) * N + col) = packh2(v2, v3);
        }
    }
}

// ---------------- selector logits + softmax + fused row bias ----------------
__global__ __launch_bounds__(256) void selector_kernel(
    const __half* __restrict__ s1, const float* __restrict__ Ws2,
    const float* __restrict__ bs2, const float* __restrict__ be2,
    float* __restrict__ wout, float* __restrict__ rbout)
{
    __shared__ float Wsm[128 * 16];
    __shared__ float bsm[16];
    __shared__ float be2s[16 * 32];
    const int tid = threadIdx.x;
    for (int i = tid; i < 2048; i += 256) Wsm[i] = Ws2[i];
    for (int i = tid; i < 512; i += 256) be2s[i] = be2[i];
    if (tid < 16) bsm[tid] = bs2[tid];
    __syncthreads();

    const int warp = tid >> 5, lane = tid & 31;
    const int row = blockIdx.x * 8 + warp;

    float v[4];
#pragma unroll
    for (int j = 0; j < 4; j++)
        v[j] = __half2float(s1[(size_t)row * 128 + j * 32 + lane]);

    float mylog = -1e30f;
#pragma unroll
    for (int e = 0; e < 16; e++) {
        float p = 0.f;
#pragma unroll
        for (int j = 0; j < 4; j++) p += v[j] * Wsm[(j * 32 + lane) * 16 + e];
#pragma unroll
        for (int off = 16; off >= 1; off >>= 1)
            p += __shfl_xor_sync(0xffffffffu, p, off);
        if (lane == e) mylog = p + bsm[e];
    }
    float m = mylog;
#pragma unroll
    for (int off = 8; off >= 1; off >>= 1)
        m = fmaxf(m, __shfl_xor_sync(0xffffffffu, m, off, 16));
    float ex = __expf(mylog - m);
    float s = ex;
#pragma unroll
    for (int off = 8; off >= 1; off >>= 1)
        s += __shfl_xor_sync(0xffffffffu, s, off, 16);
    float wv = ex / s;
    if (lane < 16) wout[(size_t)row * 16 + lane] = wv;

    float rbv = 0.f;
#pragma unroll
    for (int e = 0; e < 16; e++) {
        float we = __shfl_sync(0xffffffffu, wv, e);
        rbv += we * be2s[e * 32 + lane];
    }
    rbout[(size_t)row * 32 + lane] = rbv;
}

// ---------------- final fused GEMM (split-K x4): part = g @ We2h ------------
__global__ __launch_bounds__(256) void final_gemm(
    const __half* __restrict__ g, const __half* __restrict__ W2,
    float* __restrict__ part)
{
    __shared__ __align__(16) char AsB[128 * RSA];
    __shared__ __align__(16) char BsB[32 * RSA];

    const int tid = threadIdx.x;
    const int warp = tid >> 5, lane = tid & 31;
    const int lg = lane >> 2, lt = lane & 3;
    const int m0 = blockIdx.x * 128;
    const int kb = blockIdx.y * 1024;

    const uint32_t As = smem_u32(AsB), Bs = smem_u32(BsB);
    const int li = lane & 7, ls = lane >> 3;
    const uint32_t aAddr = As + (uint32_t)(warp * 16 + li + 8 * (ls & 1)) * RSA + (ls >> 1) * 16;
    const uint32_t bAddr = Bs + (uint32_t)(li + 8 * (ls & 1)) * RSA + (uint32_t)(8 * (ls >> 1)) * 2;

    float acc[4][4];
#pragma unroll
    for (int nf = 0; nf < 4; nf++)
#pragma unroll
        for (int k = 0; k < 4; k++) acc[nf][k] = 0.f;

    for (int kt = 0; kt < 32; kt++) {
        const int k0 = kb + kt * 32;
        __syncthreads();
#pragma unroll
        for (int j = 0; j < 2; j++) {
            int idx = tid + 256 * j;
            int r = idx >> 2, q = idx & 3;
            uint4 u = *(const uint4*)(g + (size_t)(m0 + r) * 4096 + k0 + q * 8);
            *(uint4*)(AsB + r * RSA + q * 16) = u;
        }
        if (tid < 128) {
            int krow = tid >> 2, q = tid & 3;
            uint4 u = *(const uint4*)(W2 + (size_t)(k0 + krow) * 32 + q * 8);
            *(uint4*)(BsB + krow * RSA + q * 16) = u;
        }
        __syncthreads();

#pragma unroll
        for (int h = 0; h < 2; h++) {
            uint32_t a[4];
            LDSM_X4(a, aAddr + h * 32);
            uint32_t b[2][4];
#pragma unroll
            for (int nfp = 0; nfp < 2; nfp++)
                LDSM_X4_T(b[nfp], bAddr + nfp * 32 + h * (16 * RSA));
#pragma unroll
            for (int nf = 0; nf < 4; nf++)
                mma_f16(acc[nf], a, b[nf >> 1][(nf & 1) * 2], b[nf >> 1][(nf & 1) * 2 + 1]);
        }
    }

    float* P = part + (size_t)blockIdx.y * ((size_t)BATCH * 32);
    int row = m0 + warp * 16 + lg;
#pragma unroll
    for (int nf = 0; nf < 4; nf++) {
        int col = nf * 8 + lt * 2;
        *(float2*)(P + (size_t)row * 32 + col)       = make_float2(acc[nf][0], acc[nf][1]);
        *(float2*)(P + (size_t)(row + 8) * 32 + col) = make_float2(acc[nf][2], acc[nf][3]);
    }
}

// ---------------- split-K reduce + row-bias add -----------------------------
__global__ __launch_bounds__(256) void reduce_final(
    const float* __restrict__ part, const float* __restrict__ rb,
    float* __restrict__ out)
{
    size_t idx = (size_t)blockIdx.x * 256 + threadIdx.x;
    const size_t S = (size_t)BATCH * 32 / 4;
    const float4* p4 = (const float4*)part;
    float4 r = ((const float4*)rb)[idx];
#pragma unroll
    for (int s = 0; s < 4; s++) {
        float4 p = p4[s * S + idx];
        r.x += p.x; r.y += p.y; r.z += p.z; r.w += p.w;
    }
    ((float4*)out)[idx] = r;
}

// ---------------- launch -----------------------------------------------------
extern "C" void kernel_launch(void* const* d_in, const int* in_sizes, int n_in,
                              void* d_out, int out_size)
{
    const float* obs = (const float*)d_in[0];
    const float* Wb0 = (const float*)d_in[1];  const float* bb0 = (const float*)d_in[2];
    const float* Wb1 = (const float*)d_in[3];  const float* bb1 = (const float*)d_in[4];
    const float* Wb2 = (const float*)d_in[5];  const float* bb2 = (const float*)d_in[6];
    const float* We1 = (const float*)d_in[7];  const float* be1 = (const float*)d_in[8];
    const float* We2 = (const float*)d_in[9];  const float* be2 = (const float*)d_in[10];
    const float* Ws0 = (const float*)d_in[11]; const float* bs0 = (const float*)d_in[12];
    const float* Ws1 = (const float*)d_in[13]; const float* bs1 = (const float*)d_in[14];
    const float* Ws2 = (const float*)d_in[15]; const float* bs2 = (const float*)d_in[16];
    float* out = (float*)d_out;

    __half *obsh, *h0, *h1, *h2, *s0, *s1, *eh;
    __half *Wb0h, *Wb1h, *Wb2h, *Ws0h, *Ws1h, *We1h, *We2h;
    float *w, *rb, *part;
    cudaGetSymbolAddress((void**)&obsh, g_obsh);
    cudaGetSymbolAddress((void**)&h0, g_h0);
    cudaGetSymbolAddress((void**)&h1, g_h1);
    cudaGetSymbolAddress((void**)&h2, g_h2);
    cudaGetSymbolAddress((void**)&s0, g_s0);
    cudaGetSymbolAddress((void**)&s1, g_s1);
    cudaGetSymbolAddress((void**)&w,  g_w);
    cudaGetSymbolAddress((void**)&rb, g_rb);
    cudaGetSymbolAddress((void**)&eh, g_eh);
    cudaGetSymbolAddress((void**)&part, g_part);
    cudaGetSymbolAddress((void**)&Wb0h, g_Wb0h);
    cudaGetSymbolAddress((void**)&Wb1h, g_Wb1h);
    cudaGetSymbolAddress((void**)&Wb2h, g_Wb2h);
    cudaGetSymbolAddress((void**)&Ws0h, g_Ws0h);
    cudaGetSymbolAddress((void**)&Ws1h, g_Ws1h);
    cudaGetSymbolAddress((void**)&We1h, g_We1h);
    cudaGetSymbolAddress((void**)&We2h, g_We2h);

    // dynamic smem opt-in
    constexpr int RSB256 = 256 * 2 + 16, RSB128 = 128 * 2 + 16;
    constexpr int SM256 = 2 * (128 * RSA + 32 * RSB256) + 256 * 4;   // 55296
    constexpr int SM128 = 2 * (128 * RSA + 32 * RSB128) + 128 * 4;   // 38400
    cudaFuncSetAttribute((const void*)tc_gemm<256, true, false, false>,
                         cudaFuncAttributeMaxDynamicSharedMemorySize, SM256);
    cudaFuncSetAttribute((const void*)tc_gemm<128, true, false, false>,
                         cudaFuncAttributeMaxDynamicSharedMemorySize, SM128);
    cudaFuncSetAttribute((const void*)tc_gemm<256, true, true, true>,
                         cudaFuncAttributeMaxDynamicSharedMemorySize, SM256);

    // fp32 -> fp16 conversions (obs + all GEMM weights)
    auto cvt = [](const float* s, __half* d, size_t n) {
        size_t n8 = n / 8;
        f2h_kernel<<<(unsigned)((n8 + 255) / 256), 256>>>(s, d, n8);
    };
    cvt(obs, obsh, (size_t)BATCH * 512);
    cvt(Wb0, Wb0h, 512 * 1024);
    cvt(Wb1, Wb1h, 1024 * 1024);
    cvt(Wb2, Wb2h, 1024 * 512);
    cvt(Ws0, Ws0h, 512 * 256);
    cvt(Ws1, Ws1h, 256 * 128);
    cvt(We1, We1h, 16 * 512 * 256);
    cvt(We2, We2h, 4096 * 32);

    const int MB = BATCH / 128;   // 512

    // selector chain first (w needed by experts-L1 epilogue)
    tc_gemm<256, true, false, false><<<dim3(1, MB), 256, SM256>>>(obsh, Ws0h, bs0, nullptr, s0, 512, 256);
    tc_gemm<128, true, false, false><<<dim3(1, MB), 256, SM128>>>(s0, Ws1h, bs1, nullptr, s1, 256, 128);
    selector_kernel<<<BATCH / 8, 256>>>(s1, Ws2, bs2, be2, w, rb);

    // backbone
    tc_gemm<256, true, false, false><<<dim3(4, MB), 256, SM256>>>(obsh, Wb0h, bb0, nullptr, h0, 512, 1024);
    tc_gemm<256, true, false, false><<<dim3(4, MB), 256, SM256>>>(h0, Wb1h, bb1, nullptr, h1, 1024, 1024);
    tc_gemm<256, true, false, false><<<dim3(2, MB), 256, SM256>>>(h1, Wb2h, bb2, nullptr, h2, 1024, 512);

    // experts layer 1, w folded into epilogue: g = relu(h2 @ We1 + be1) * w
    tc_gemm<256, true, true, true><<<dim3(16, MB), 256, SM256>>>(h2, We1h, be1, w, eh, 512, 4096);

    // fusion: out = g @ We2flat + rb  (split-K x4 + reduce)
    final_gemm<<<dim3(MB, 4), 256>>>(eh, We2h, part);
    reduce_final<<<(BATCH * 32 / 4) / 256, 256>>>(part, rb, out);
}

// round 8
// speedup vs baseline: 2.3944x; 1.0498x over previous
#include <cuda_runtime.h>
#include <cuda_fp16.h>
#include <cstdint>

#define BATCH 65536
#define RSA 80     // A smem row: 32 halfs (64B) + 16B pad
#define RSG 528    // g smem row: 256 halfs (512B) + 16B pad

// ---------------- scratch (device globals; no allocation allowed) ----------
__device__ __half g_obsh[(size_t)BATCH * 512];
__device__ __half g_h0[(size_t)BATCH * 1024];
__device__ __half g_h1[(size_t)BATCH * 1024];
__device__ __half g_h2[(size_t)BATCH * 512];
__device__ __half g_s0[(size_t)BATCH * 256];
__device__ __half g_s1[(size_t)BATCH * 128];
__device__ float  g_w [(size_t)BATCH * 16];
__device__ float  g_rb[(size_t)BATCH * 32];
__device__ float  g_part[(size_t)16 * BATCH * 32];   // per-expert partials
// fp16 weights (converted once per replay; deterministic)
__device__ __half g_Wb0h[512 * 1024];
__device__ __half g_Wb1h[1024 * 1024];
__device__ __half g_Wb2h[1024 * 512];
__device__ __half g_Ws0h[512 * 256];
__device__ __half g_Ws1h[256 * 128];
__device__ __half g_We1h[16 * 512 * 256];
__device__ __half g_We2h[4096 * 32];

// ---------------- helpers ---------------------------------------------------
__device__ __forceinline__ uint32_t smem_u32(const void* p) {
    uint32_t a;
    asm("{ .reg .u64 t; cvta.to.shared.u64 t, %1; cvt.u32.u64 %0, t; }" : "=r"(a) : "l"(p));
    return a;
}
__device__ __forceinline__ void mma_f16(float* d, const uint32_t* a, uint32_t b0, uint32_t b1) {
    asm volatile(
        "mma.sync.aligned.m16n8k16.row.col.f32.f16.f16.f32 "
        "{%0,%1,%2,%3}, {%4,%5,%6,%7}, {%8,%9}, {%0,%1,%2,%3};\n"
        : "+f"(d[0]), "+f"(d[1]), "+f"(d[2]), "+f"(d[3])
        : "r"(a[0]), "r"(a[1]), "r"(a[2]), "r"(a[3]), "r"(b0), "r"(b1));
}
#define LDSM_X4(r, addr) \
    asm volatile("ldmatrix.sync.aligned.m8n8.x4.shared.b16 {%0,%1,%2,%3}, [%4];" \
        : "=r"((r)[0]), "=r"((r)[1]), "=r"((r)[2]), "=r"((r)[3]) : "r"(addr))
#define LDSM_X4_T(r, addr) \
    asm volatile("ldmatrix.sync.aligned.m8n8.x4.trans.shared.b16 {%0,%1,%2,%3}, [%4];" \
        : "=r"((r)[0]), "=r"((r)[1]), "=r"((r)[2]), "=r"((r)[3]) : "r"(addr))
#define CP_ASYNC16(dst, src) \
    asm volatile("cp.async.cg.shared.global [%0], [%1], 16;\n" :: "r"(dst), "l"(src))
#define CP_COMMIT() asm volatile("cp.async.commit_group;\n" ::: "memory")
#define CP_WAIT1()  asm volatile("cp.async.wait_group 1;\n" ::: "memory")
#define CP_WAIT0()  asm volatile("cp.async.wait_group 0;\n" ::: "memory")

__device__ __forceinline__ uint32_t packh2(float lo, float hi) {
    __half2 h = __floats2half2_rn(lo, hi);
    return *(uint32_t*)&h;
}

// ---------------- fp32 -> fp16 conversion (8 elems/thread) ------------------
__global__ __launch_bounds__(256) void f2h_kernel(
    const float* __restrict__ src, __half* __restrict__ dst, size_t n8)
{
    size_t i = (size_t)blockIdx.x * 256 + threadIdx.x;
    if (i >= n8) return;
    float4 a = ((const float4*)src)[2 * i];
    float4 b = ((const float4*)src)[2 * i + 1];
    uint4 u;
    u.x = packh2(a.x, a.y); u.y = packh2(a.z, a.w);
    u.z = packh2(b.x, b.y); u.w = packh2(b.z, b.w);
    ((uint4*)dst)[i] = u;
}

// ---------------- generic GEMM: C(half) = act(A @ B + bias) -----------------
// 128 x BN block, 256 thr, 8 warps (2x4), warp tile 64 x (BN/4).
// 3-stage cp.async pipeline, ldmatrix fragments, fp16 in / fp16 out.
template<int BN, bool RELU>
__global__ __launch_bounds__(256, 1) void tc_gemm(
    const __half* __restrict__ A, const __half* __restrict__ B,
    const float* __restrict__ bias, __half* __restrict__ C, int K, int N)
{
    extern __shared__ char smem[];
    constexpr int RSB = BN * 2 + 16;
    constexpr int ASZ = 128 * RSA;
    constexpr int STG = ASZ + 32 * RSB;
    constexpr int CPR = BN / 8;
    constexpr int NF  = BN / 32;
    float* sbias = (float*)(smem + 3 * STG);

    const int tid = threadIdx.x, warp = tid >> 5, lane = tid & 31;
    const int rA = (warp >> 2) * 64, cB = (warp & 3) * (BN / 4);
    const int lg = lane >> 2, lt = lane & 3;
    const int m0 = blockIdx.y * 128, n0 = blockIdx.x * BN;

    const __half* Bp = B + n0;

    for (int i = tid; i < BN; i += 256) sbias[i] = bias[n0 + i];

    const uint32_t smb = smem_u32(smem);
    const int li = lane & 7, ls = lane >> 3;
    const uint32_t aOff = (uint32_t)(rA + li + 8 * (ls & 1)) * RSA + (ls >> 1) * 16;
    const uint32_t bOff = ASZ + (uint32_t)(li + 8 * (ls & 1)) * RSB
                        + (uint32_t)(cB + 8 * (ls >> 1)) * 2;

    float acc[4][NF][4];
#pragma unroll
    for (int i = 0; i < 4; i++)
#pragma unroll
        for (int j = 0; j < NF; j++)
#pragma unroll
            for (int k = 0; k < 4; k++) acc[i][j][k] = 0.f;

    const int NT = K >> 5;

#define LOAD_STAGE(t, buf)                                                     \
    {                                                                          \
        const uint32_t base = smb + (buf) * STG;                               \
        const int k0 = (t) * 32;                                               \
        _Pragma("unroll")                                                      \
        for (int j = 0; j < 2; j++) {                                          \
            int i = tid + 256 * j;                                             \
            int r = i >> 2, q = i & 3;                                         \
            CP_ASYNC16(base + r * RSA + q * 16,                                \
                       A + (size_t)(m0 + r) * K + k0 + q * 8);                 \
        }                                                                      \
        _Pragma("unroll")                                                      \
        for (int j = 0; j < BN / 64; j++) {                                    \
            int i = tid + 256 * j;                                             \
            int krow = i / CPR, c16 = i % CPR;                                 \
            CP_ASYNC16(base + ASZ + krow * RSB + c16 * 16,                     \
                       Bp + (size_t)(k0 + krow) * N + c16 * 8);                \
        }                                                                      \
        CP_COMMIT();                                                           \
    }

    LOAD_STAGE(0, 0);
    LOAD_STAGE(1, 1);

    int buf = 0, nbuf = 2;
    for (int t = 0; t < NT; t++) {
        if (t + 1 < NT) { CP_WAIT1(); } else { CP_WAIT0(); }
        __syncthreads();
        if (t + 2 < NT) { LOAD_STAGE(t + 2, nbuf); }

        const uint32_t base = smb + buf * STG;
#pragma unroll
        for (int h = 0; h < 2; h++) {
            uint32_t a[4][4];
#pragma unroll
            for (int mf = 0; mf < 4; mf++)
                LDSM_X4(a[mf], base + aOff + mf * (16 * RSA) + h * 32);
            uint32_t b[NF / 2][4];
#pragma unroll
            for (int nfp = 0; nfp < NF / 2; nfp++)
                LDSM_X4_T(b[nfp], base + bOff + nfp * 32 + h * (16 * RSB));
#pragma unroll
            for (int mf = 0; mf < 4; mf++)
#pragma unroll
                for (int nf = 0; nf < NF; nf++)
                    mma_f16(acc[mf][nf], a[mf],
                            b[nf >> 1][(nf & 1) * 2], b[nf >> 1][(nf & 1) * 2 + 1]);
        }
        __syncthreads();
        buf = (buf == 2) ? 0 : buf + 1;
        nbuf = (nbuf == 2) ? 0 : nbuf + 1;
    }
#undef LOAD_STAGE

#pragma unroll
    for (int mf = 0; mf < 4; mf++) {
        int row = m0 + rA + mf * 16 + lg;
#pragma unroll
        for (int nf = 0; nf < NF; nf++) {
            int cl = cB + nf * 8 + lt * 2;
            int col = n0 + cl;
            float b0 = sbias[cl], b1 = sbias[cl + 1];
            float v0 = acc[mf][nf][0] + b0, v1 = acc[mf][nf][1] + b1;
            float v2 = acc[mf][nf][2] + b0, v3 = acc[mf][nf][3] + b1;
            if (RELU) {
                v0 = fmaxf(v0, 0.f); v1 = fmaxf(v1, 0.f);
                v2 = fmaxf(v2, 0.f); v3 = fmaxf(v3, 0.f);
            }
            *(uint32_t*)(C + (size_t)row * N + col)       = packh2(v0, v1);
            *(uint32_t*)(C + (size_t)(row + 8) * N + col) = packh2(v2, v3);
        }
    }
}

// ---------------- fused expert kernel ---------------------------------------
// Block (e = blockIdx.x, m0 = blockIdx.y*128):
//   g = relu(h2[m0:m0+128] @ We1[e] + be1[e]) * w[:, e]       (128x256)
//   part[e][m0:m0+128] = g @ We2[e]                            (128x32, fp32)
__global__ __launch_bounds__(256, 1) void expert_gemm(
    const __half* __restrict__ A, const __half* __restrict__ We1,
    const float* __restrict__ be1, const float* __restrict__ wsel,
    const __half* __restrict__ We2, float* __restrict__ part)
{
    extern __shared__ char smem[];
    constexpr int BN = 256, K = 512;
    constexpr int RSB = BN * 2 + 16;
    constexpr int ASZ = 128 * RSA;
    constexpr int STG = ASZ + 32 * RSB;        // 27136
    constexpr int CPR = BN / 8;                // 32
    constexpr int NF  = 8;
    constexpr int GBUF = 0;                    // overlay: g tile 128 x RSG
    constexpr int W2S  = 128 * RSG;            // We2 smem: 256 rows x 80B
    float* sbias = (float*)(smem + 3 * STG);   // 81408..82432 (beyond GBUF)

    const int tid = threadIdx.x, warp = tid >> 5, lane = tid & 31;
    const int rA = (warp >> 2) * 64, cB = (warp & 3) * 64;
    const int lg = lane >> 2, lt = lane & 3;
    const int m0 = blockIdx.y * 128;
    const int e  = blockIdx.x;

    const __half* Bp = We1 + (size_t)e * K * 256;

    for (int i = tid; i < BN; i += 256) sbias[i] = be1[e * 256 + i];

    const uint32_t smb = smem_u32(smem);
    const int li = lane & 7, ls = lane >> 3;
    const uint32_t aOff = (uint32_t)(rA + li + 8 * (ls & 1)) * RSA + (ls >> 1) * 16;
    const uint32_t bOff = ASZ + (uint32_t)(li + 8 * (ls & 1)) * RSB
                        + (uint32_t)(cB + 8 * (ls >> 1)) * 2;

    float acc[4][NF][4];
#pragma unroll
    for (int i = 0; i < 4; i++)
#pragma unroll
        for (int j = 0; j < NF; j++)
#pragma unroll
            for (int k = 0; k < 4; k++) acc[i][j][k] = 0.f;

    const int NT = K >> 5;   // 16

#define LOAD_STAGE(t, bufi)                                                    \
    {                                                                          \
        const uint32_t base = smb + (bufi) * STG;                              \
        const int k0 = (t) * 32;                                               \
        _Pragma("unroll")                                                      \
        for (int j = 0; j < 2; j++) {                                          \
            int i = tid + 256 * j;                                             \
            int r = i >> 2, q = i & 3;                                         \
            CP_ASYNC16(base + r * RSA + q * 16,                                \
                       A + (size_t)(m0 + r) * K + k0 + q * 8);                 \
        }                                                                      \
        _Pragma("unroll")                                                      \
        for (int j = 0; j < 4; j++) {                                          \
            int i = tid + 256 * j;                                             \
            int krow = i / CPR, c16 = i % CPR;                                 \
            CP_ASYNC16(base + ASZ + krow * RSB + c16 * 16,                     \
                       Bp + (size_t)(k0 + krow) * 256 + c16 * 8);              \
        }                                                                      \
        CP_COMMIT();                                                           \
    }

    LOAD_STAGE(0, 0);
    LOAD_STAGE(1, 1);

    int buf = 0, nbuf = 2;
    for (int t = 0; t < NT; t++) {
        if (t + 1 < NT) { CP_WAIT1(); } else { CP_WAIT0(); }
        __syncthreads();
        if (t + 2 < NT) { LOAD_STAGE(t + 2, nbuf); }

        const uint32_t base = smb + buf * STG;
#pragma unroll
        for (int h = 0; h < 2; h++) {
            uint32_t a[4][4];
#pragma unroll
            for (int mf = 0; mf < 4; mf++)
                LDSM_X4(a[mf], base + aOff + mf * (16 * RSA) + h * 32);
            uint32_t b[NF / 2][4];
#pragma unroll
            for (int nfp = 0; nfp < NF / 2; nfp++)
                LDSM_X4_T(b[nfp], base + bOff + nfp * 32 + h * (16 * RSB));
#pragma unroll
            for (int mf = 0; mf < 4; mf++)
#pragma unroll
                for (int nf = 0; nf < NF; nf++)
                    mma_f16(acc[mf][nf], a[mf],
                            b[nf >> 1][(nf & 1) * 2], b[nf >> 1][(nf & 1) * 2 + 1]);
        }
        __syncthreads();
        buf = (buf == 2) ? 0 : buf + 1;
        nbuf = (nbuf == 2) ? 0 : nbuf + 1;
    }
#undef LOAD_STAGE

    // ---- epilogue 1: bias + relu + w-scale, pack g into smem ----
#pragma unroll
    for (int mf = 0; mf < 4; mf++) {
        int row = m0 + rA + mf * 16 + lg;
        int lr0 = rA + mf * 16 + lg;
        float ws0 = wsel[(size_t)row * 16 + e];
        float ws1 = wsel[(size_t)(row + 8) * 16 + e];
#pragma unroll
        for (int nf = 0; nf < NF; nf++) {
            int cl = cB + nf * 8 + lt * 2;
            float b0 = sbias[cl], b1 = sbias[cl + 1];
            float v0 = fmaxf(acc[mf][nf][0] + b0, 0.f) * ws0;
            float v1 = fmaxf(acc[mf][nf][1] + b1, 0.f) * ws0;
            float v2 = fmaxf(acc[mf][nf][2] + b0, 0.f) * ws1;
            float v3 = fmaxf(acc[mf][nf][3] + b1, 0.f) * ws1;
            *(uint32_t*)(smem + GBUF + lr0 * RSG + cl * 2)       = packh2(v0, v1);
            *(uint32_t*)(smem + GBUF + (lr0 + 8) * RSG + cl * 2) = packh2(v2, v3);
        }
    }
    __syncthreads();

    // ---- load We2[e] (256x32 half) into smem, stride 80 ----
#pragma unroll
    for (int j = 0; j < 4; j++) {
        int i = tid + 256 * j;
        int hrow = i >> 2, q = i & 3;
        uint4 u = *(const uint4*)(We2 + ((size_t)e * 256 + hrow) * 32 + q * 8);
        *(uint4*)(smem + W2S + hrow * RSA + q * 16) = u;
    }
    __syncthreads();

    // ---- mini-GEMM: part_tile = g(128x256) @ We2s(256x32) ----
    {
        const uint32_t aAddr2 = smb + GBUF
            + (uint32_t)(warp * 16 + li + 8 * (ls & 1)) * RSG + (ls >> 1) * 16;
        const uint32_t bAddr2 = smb + W2S
            + (uint32_t)(li + 8 * (ls & 1)) * RSA + (uint32_t)(8 * (ls >> 1)) * 2;

        float acc2[4][4];
#pragma unroll
        for (int nf = 0; nf < 4; nf++)
#pragma unroll
            for (int k = 0; k < 4; k++) acc2[nf][k] = 0.f;

#pragma unroll
        for (int ks = 0; ks < 16; ks++) {
            uint32_t a[4];
            LDSM_X4(a, aAddr2 + ks * 32);
            uint32_t b[2][4];
#pragma unroll
            for (int nfp = 0; nfp < 2; nfp++)
                LDSM_X4_T(b[nfp], bAddr2 + nfp * 32 + ks * (16 * RSA));
#pragma unroll
            for (int nf = 0; nf < 4; nf++)
                mma_f16(acc2[nf], a, b[nf >> 1][(nf & 1) * 2], b[nf >> 1][(nf & 1) * 2 + 1]);
        }

        float* P = part + (size_t)e * ((size_t)BATCH * 32);
        int row = m0 + warp * 16 + lg;
#pragma unroll
        for (int nf = 0; nf < 4; nf++) {
            int col = nf * 8 + lt * 2;
            *(float2*)(P + (size_t)row * 32 + col)       = make_float2(acc2[nf][0], acc2[nf][1]);
            *(float2*)(P + (size_t)(row + 8) * 32 + col) = make_float2(acc2[nf][2], acc2[nf][3]);
        }
    }
}

// ---------------- selector logits + softmax + fused row bias ----------------
__global__ __launch_bounds__(256) void selector_kernel(
    const __half* __restrict__ s1, const float* __restrict__ Ws2,
    const float* __restrict__ bs2, const float* __restrict__ be2,
    float* __restrict__ wout, float* __restrict__ rbout)
{
    __shared__ float Wsm[128 * 16];
    __shared__ float bsm[16];
    __shared__ float be2s[16 * 32];
    const int tid = threadIdx.x;
    for (int i = tid; i < 2048; i += 256) Wsm[i] = Ws2[i];
    for (int i = tid; i < 512; i += 256) be2s[i] = be2[i];
    if (tid < 16) bsm[tid] = bs2[tid];
    __syncthreads();

    const int warp = tid >> 5, lane = tid & 31;
    const int row = blockIdx.x * 8 + warp;

    float v[4];
#pragma unroll
    for (int j = 0; j < 4; j++)
        v[j] = __half2float(s1[(size_t)row * 128 + j * 32 + lane]);

    float mylog = -1e30f;
#pragma unroll
    for (int e = 0; e < 16; e++) {
        float p = 0.f;
#pragma unroll
        for (int j = 0; j < 4; j++) p += v[j] * Wsm[(j * 32 + lane) * 16 + e];
#pragma unroll
        for (int off = 16; off >= 1; off >>= 1)
            p += __shfl_xor_sync(0xffffffffu, p, off);
        if (lane == e) mylog = p + bsm[e];
    }
    float m = mylog;
#pragma unroll
    for (int off = 8; off >= 1; off >>= 1)
        m = fmaxf(m, __shfl_xor_sync(0xffffffffu, m, off, 16));
    float ex = __expf(mylog - m);
    float s = ex;
#pragma unroll
    for (int off = 8; off >= 1; off >>= 1)
        s += __shfl_xor_sync(0xffffffffu, s, off, 16);
    float wv = ex / s;
    if (lane < 16) wout[(size_t)row * 16 + lane] = wv;

    float rbv = 0.f;
#pragma unroll
    for (int e = 0; e < 16; e++) {
        float we = __shfl_sync(0xffffffffu, wv, e);
        rbv += we * be2s[e * 32 + lane];
    }
    rbout[(size_t)row * 32 + lane] = rbv;
}

// ---------------- 16-way partial reduce + row-bias --------------------------
__global__ __launch_bounds__(256) void reduce_final(
    const float* __restrict__ part, const float* __restrict__ rb,
    float* __restrict__ out)
{
    size_t idx = (size_t)blockIdx.x * 256 + threadIdx.x;   // float4 units
    const size_t S = (size_t)BATCH * 32 / 4;
    const float4* p4 = (const float4*)part;
    float4 r = ((const float4*)rb)[idx];
#pragma unroll
    for (int s = 0; s < 16; s++) {
        float4 p = p4[s * S + idx];
        r.x += p.x; r.y += p.y; r.z += p.z; r.w += p.w;
    }
    ((float4*)out)[idx] = r;
}

// ---------------- launch -----------------------------------------------------
extern "C" void kernel_launch(void* const* d_in, const int* in_sizes, int n_in,
                              void* d_out, int out_size)
{
    const float* obs = (const float*)d_in[0];
    const float* Wb0 = (const float*)d_in[1];  const float* bb0 = (const float*)d_in[2];
    const float* Wb1 = (const float*)d_in[3];  const float* bb1 = (const float*)d_in[4];
    const float* Wb2 = (const float*)d_in[5];  const float* bb2 = (const float*)d_in[6];
    const float* We1 = (const float*)d_in[7];  const float* be1 = (const float*)d_in[8];
    const float* We2 = (const float*)d_in[9];  const float* be2 = (const float*)d_in[10];
    const float* Ws0 = (const float*)d_in[11]; const float* bs0 = (const float*)d_in[12];
    const float* Ws1 = (const float*)d_in[13]; const float* bs1 = (const float*)d_in[14];
    const float* Ws2 = (const float*)d_in[15]; const float* bs2 = (const float*)d_in[16];
    float* out = (float*)d_out;

    __half *obsh, *h0, *h1, *h2, *s0, *s1;
    __half *Wb0h, *Wb1h, *Wb2h, *Ws0h, *Ws1h, *We1h, *We2h;
    float *w, *rb, *part;
    cudaGetSymbolAddress((void**)&obsh, g_obsh);
    cudaGetSymbolAddress((void**)&h0, g_h0);
    cudaGetSymbolAddress((void**)&h1, g_h1);
    cudaGetSymbolAddress((void**)&h2, g_h2);
    cudaGetSymbolAddress((void**)&s0, g_s0);
    cudaGetSymbolAddress((void**)&s1, g_s1);
    cudaGetSymbolAddress((void**)&w,  g_w);
    cudaGetSymbolAddress((void**)&rb, g_rb);
    cudaGetSymbolAddress((void**)&part, g_part);
    cudaGetSymbolAddress((void**)&Wb0h, g_Wb0h);
    cudaGetSymbolAddress((void**)&Wb1h, g_Wb1h);
    cudaGetSymbolAddress((void**)&Wb2h, g_Wb2h);
    cudaGetSymbolAddress((void**)&Ws0h, g_Ws0h);
    cudaGetSymbolAddress((void**)&Ws1h, g_Ws1h);
    cudaGetSymbolAddress((void**)&We1h, g_We1h);
    cudaGetSymbolAddress((void**)&We2h, g_We2h);

    // dynamic smem sizes
    constexpr int RSB256 = 256 * 2 + 16, RSB128 = 128 * 2 + 16;
    constexpr int STG256 = 128 * RSA + 32 * RSB256;          // 27136
    constexpr int STG128 = 128 * RSA + 32 * RSB128;          // 18944
    constexpr int SM256 = 3 * STG256 + 256 * 4;              // 82432
    constexpr int SM128 = 3 * STG128 + 128 * 4;              // 57344
    constexpr int SMEXP = 3 * STG256 + 256 * 4 > 128 * RSG + 256 * RSA + 0
                        ? 3 * STG256 + 256 * 4 + 2048        // cover both phases
                        : 128 * RSG + 256 * RSA;
    cudaFuncSetAttribute((const void*)tc_gemm<256, true>,
                         cudaFuncAttributeMaxDynamicSharedMemorySize, SM256);
    cudaFuncSetAttribute((const void*)tc_gemm<128, true>,
                         cudaFuncAttributeMaxDynamicSharedMemorySize, SM128);
    cudaFuncSetAttribute((const void*)expert_gemm,
                         cudaFuncAttributeMaxDynamicSharedMemorySize, 90112);

    // fp32 -> fp16 conversions
    auto cvt = [](const float* s, __half* d, size_t n) {
        size_t n8 = n / 8;
        f2h_kernel<<<(unsigned)((n8 + 255) / 256), 256>>>(s, d, n8);
    };
    cvt(obs, obsh, (size_t)BATCH * 512);
    cvt(Wb0, Wb0h, 512 * 1024);
    cvt(Wb1, Wb1h, 1024 * 1024);
    cvt(Wb2, Wb2h, 1024 * 512);
    cvt(Ws0, Ws0h, 512 * 256);
    cvt(Ws1, Ws1h, 256 * 128);
    cvt(We1, We1h, 16 * 512 * 256);
    cvt(We2, We2h, 4096 * 32);

    const int MB = BATCH / 128;   // 512

    // selector chain (w needed by expert kernel)
    tc_gemm<256, true><<<dim3(1, MB), 256, SM256>>>(obsh, Ws0h, bs0, s0, 512, 256);
    tc_gemm<128, true><<<dim3(1, MB), 256, SM128>>>(s0, Ws1h, bs1, s1, 256, 128);
    selector_kernel<<<BATCH / 8, 256>>>(s1, Ws2, bs2, be2, w, rb);

    // backbone
    tc_gemm<256, true><<<dim3(4, MB), 256, SM256>>>(obsh, Wb0h, bb0, h0, 512, 1024);
    tc_gemm<256, true><<<dim3(4, MB), 256, SM256>>>(h0, Wb1h, bb1, h1, 1024, 1024);
    tc_gemm<256, true><<<dim3(2, MB), 256, SM256>>>(h1, Wb2h, bb2, h2, 1024, 512);

    // fused experts: per-expert partials (L1 + L2 + weighting in one kernel)
    expert_gemm<<<dim3(16, MB), 256, 90112>>>(h2, We1h, be1, w, We2h, part);

    // final: out = sum_e part[e] + rb
    reduce_final<<<(BATCH * 32 / 4) / 256, 256>>>(part, rb, out);
}

// round 9
// speedup vs baseline: 2.4692x; 1.0312x over previous
#include <cuda_runtime.h>
#include <cuda_fp16.h>
#include <cstdint>

#define BATCH 65536
#define RSA 80     // A smem row: 32 halfs (64B) + 16B pad
#define RSG 528    // g smem row: 256 halfs (512B) + 16B pad

// ---------------- scratch (device globals; no allocation allowed) ----------
__device__ __half g_obsh[(size_t)BATCH * 512];
__device__ __half g_h0s0[(size_t)BATCH * 1280];   // [h0 | s0] packed
__device__ __half g_h1[(size_t)BATCH * 1024];
__device__ __half g_h2[(size_t)BATCH * 512];
__device__ __half g_s1[(size_t)BATCH * 128];
__device__ float  g_w [(size_t)BATCH * 16];
__device__ float  g_rb[(size_t)BATCH * 32];
__device__ float  g_part[(size_t)16 * BATCH * 32];
// fp16 weights (converted once per replay; deterministic)
__device__ __half g_W0cat[512 * 1280];            // [Wb0 | Ws0]
__device__ float  g_b0cat[1280];
__device__ __half g_Wb1h[1024 * 1024];
__device__ __half g_Wb2h[1024 * 512];
__device__ __half g_Ws1h[256 * 128];
__device__ __half g_We1h[16 * 512 * 256];
__device__ __half g_We2h[4096 * 32];

// ---------------- helpers ---------------------------------------------------
__device__ __forceinline__ uint32_t smem_u32(const void* p) {
    uint32_t a;
    asm("{ .reg .u64 t; cvta.to.shared.u64 t, %1; cvt.u32.u64 %0, t; }" : "=r"(a) : "l"(p));
    return a;
}
__device__ __forceinline__ void mma_f16(float* d, const uint32_t* a, uint32_t b0, uint32_t b1) {
    asm volatile(
        "mma.sync.aligned.m16n8k16.row.col.f32.f16.f16.f32 "
        "{%0,%1,%2,%3}, {%4,%5,%6,%7}, {%8,%9}, {%0,%1,%2,%3};\n"
        : "+f"(d[0]), "+f"(d[1]), "+f"(d[2]), "+f"(d[3])
        : "r"(a[0]), "r"(a[1]), "r"(a[2]), "r"(a[3]), "r"(b0), "r"(b1));
}
#define LDSM_X4(r, addr) \
    asm volatile("ldmatrix.sync.aligned.m8n8.x4.shared.b16 {%0,%1,%2,%3}, [%4];" \
        : "=r"((r)[0]), "=r"((r)[1]), "=r"((r)[2]), "=r"((r)[3]) : "r"(addr))
#define LDSM_X4_T(r, addr) \
    asm volatile("ldmatrix.sync.aligned.m8n8.x4.trans.shared.b16 {%0,%1,%2,%3}, [%4];" \
        : "=r"((r)[0]), "=r"((r)[1]), "=r"((r)[2]), "=r"((r)[3]) : "r"(addr))
#define CP_ASYNC16(dst, src) \
    asm volatile("cp.async.cg.shared.global [%0], [%1], 16;\n" :: "r"(dst), "l"(src))
#define CP_COMMIT() asm volatile("cp.async.commit_group;\n" ::: "memory")
#define CP_WAIT1()  asm volatile("cp.async.wait_group 1;\n" ::: "memory")
#define CP_WAIT0()  asm volatile("cp.async.wait_group 0;\n" ::: "memory")

__device__ __forceinline__ uint32_t packh2(float lo, float hi) {
    __half2 h = __floats2half2_rn(lo, hi);
    return *(uint32_t*)&h;
}

// ---------------- fp32 -> fp16 conversion (8 elems/thread) ------------------
__global__ __launch_bounds__(256) void f2h_kernel(
    const float* __restrict__ src, __half* __restrict__ dst, size_t n8)
{
    size_t i = (size_t)blockIdx.x * 256 + threadIdx.x;
    if (i >= n8) return;
    float4 a = ((const float4*)src)[2 * i];
    float4 b = ((const float4*)src)[2 * i + 1];
    uint4 u;
    u.x = packh2(a.x, a.y); u.y = packh2(a.z, a.w);
    u.z = packh2(b.x, b.y); u.w = packh2(b.z, b.w);
    ((uint4*)dst)[i] = u;
}

// ---------------- concat-convert: W0cat = [Wb0 | Ws0] fp16, b0cat -----------
__global__ __launch_bounds__(256) void cat_kernel(
    const float* __restrict__ Wb0, const float* __restrict__ Ws0,
    const float* __restrict__ bb0, const float* __restrict__ bs0,
    __half* __restrict__ Wcat, float* __restrict__ bcat)
{
    // grid: 512 * 1280 / 256 blocks; each thread one element
    size_t i = (size_t)blockIdx.x * 256 + threadIdx.x;
    if (i < (size_t)512 * 1280) {
        int k = (int)(i / 1280), c = (int)(i % 1280);
        float v = (c < 1024) ? Wb0[(size_t)k * 1024 + c] : Ws0[(size_t)k * 256 + (c - 1024)];
        Wcat[i] = __float2half_rn(v);
    }
    if (i < 1280) bcat[i] = (i < 1024) ? bb0[i] : bs0[i - 1024];
}

// ---------------- generic GEMM: C(half) = act(A @ B + bias) -----------------
// 128 x BN block, 256 thr, 8 warps (2x4), warp tile 64 x (BN/4).
// 3-stage cp.async pipeline (single barrier per stage), hoisted ldmatrix.
template<int BN, bool RELU>
__global__ __launch_bounds__(256, 1) void tc_gemm(
    const __half* __restrict__ A, const __half* __restrict__ B,
    const float* __restrict__ bias, __half* __restrict__ C,
    int K, int N, int lda)
{
    extern __shared__ char smem[];
    constexpr int RSB = BN * 2 + 16;
    constexpr int ASZ = 128 * RSA;
    constexpr int STG = ASZ + 32 * RSB;
    constexpr int CPR = BN / 8;
    constexpr int NF  = BN / 32;
    float* sbias = (float*)(smem + 3 * STG);

    const int tid = threadIdx.x, warp = tid >> 5, lane = tid & 31;
    const int rA = (warp >> 2) * 64, cB = (warp & 3) * (BN / 4);
    const int lg = lane >> 2, lt = lane & 3;
    const int m0 = blockIdx.y * 128, n0 = blockIdx.x * BN;

    const __half* Bp = B + n0;

    for (int i = tid; i < BN; i += 256) sbias[i] = bias[n0 + i];

    const uint32_t smb = smem_u32(smem);
    const int li = lane & 7, ls = lane >> 3;
    const uint32_t aOff = (uint32_t)(rA + li + 8 * (ls & 1)) * RSA + (ls >> 1) * 16;
    const uint32_t bOff = ASZ + (uint32_t)(li + 8 * (ls & 1)) * RSB
                        + (uint32_t)(cB + 8 * (ls >> 1)) * 2;

    float acc[4][NF][4];
#pragma unroll
    for (int i = 0; i < 4; i++)
#pragma unroll
        for (int j = 0; j < NF; j++)
#pragma unroll
            for (int k = 0; k < 4; k++) acc[i][j][k] = 0.f;

    const int NT = K >> 5;

#define LOAD_STAGE(t, buf)                                                     \
    {                                                                          \
        const uint32_t base = smb + (buf) * STG;                               \
        const int k0 = (t) * 32;                                               \
        _Pragma("unroll")                                                      \
        for (int j = 0; j < 2; j++) {                                          \
            int i = tid + 256 * j;                                             \
            int r = i >> 2, q = i & 3;                                         \
            CP_ASYNC16(base + r * RSA + q * 16,                                \
                       A + (size_t)(m0 + r) * lda + k0 + q * 8);               \
        }                                                                      \
        _Pragma("unroll")                                                      \
        for (int j = 0; j < BN / 64; j++) {                                    \
            int i = tid + 256 * j;                                             \
            int krow = i / CPR, c16 = i % CPR;                                 \
            CP_ASYNC16(base + ASZ + krow * RSB + c16 * 16,                     \
                       Bp + (size_t)(k0 + krow) * N + c16 * 8);                \
        }                                                                      \
        CP_COMMIT();                                                           \
    }

    LOAD_STAGE(0, 0);
    LOAD_STAGE(1, 1);

    int buf = 0, nbuf = 2;
    for (int t = 0; t < NT; t++) {
        if (t + 1 < NT) { CP_WAIT1(); } else { CP_WAIT0(); }
        __syncthreads();
        if (t + 2 < NT) { LOAD_STAGE(t + 2, nbuf); }

        const uint32_t base = smb + buf * STG;
        // hoisted fragment loads for both k-halves
        uint32_t a[2][4][4];
        uint32_t b[2][NF / 2][4];
#pragma unroll
        for (int h = 0; h < 2; h++) {
#pragma unroll
            for (int mf = 0; mf < 4; mf++)
                LDSM_X4(a[h][mf], base + aOff + mf * (16 * RSA) + h * 32);
#pragma unroll
            for (int nfp = 0; nfp < NF / 2; nfp++)
                LDSM_X4_T(b[h][nfp], base + bOff + nfp * 32 + h * (16 * RSB));
        }
#pragma unroll
        for (int h = 0; h < 2; h++)
#pragma unroll
            for (int mf = 0; mf < 4; mf++)
#pragma unroll
                for (int nf = 0; nf < NF; nf++)
                    mma_f16(acc[mf][nf], a[h][mf],
                            b[h][nf >> 1][(nf & 1) * 2], b[h][nf >> 1][(nf & 1) * 2 + 1]);
        // no trailing barrier: with 3 stages, iter t+1's top barrier orders
        // the next overwrite of buffer (t+2)%3 == (t-1)%3 after compute t-1.
        buf = (buf == 2) ? 0 : buf + 1;
        nbuf = (nbuf == 2) ? 0 : nbuf + 1;
    }
#undef LOAD_STAGE

#pragma unroll
    for (int mf = 0; mf < 4; mf++) {
        int row = m0 + rA + mf * 16 + lg;
#pragma unroll
        for (int nf = 0; nf < NF; nf++) {
            int cl = cB + nf * 8 + lt * 2;
            int col = n0 + cl;
            float b0 = sbias[cl], b1 = sbias[cl + 1];
            float v0 = acc[mf][nf][0] + b0, v1 = acc[mf][nf][1] + b1;
            float v2 = acc[mf][nf][2] + b0, v3 = acc[mf][nf][3] + b1;
            if (RELU) {
                v0 = fmaxf(v0, 0.f); v1 = fmaxf(v1, 0.f);
                v2 = fmaxf(v2, 0.f); v3 = fmaxf(v3, 0.f);
            }
            *(uint32_t*)(C + (size_t)row * N + col)       = packh2(v0, v1);
            *(uint32_t*)(C + (size_t)(row + 8) * N + col) = packh2(v2, v3);
        }
    }
}

// ---------------- fused expert kernel ---------------------------------------
__global__ __launch_bounds__(256, 1) void expert_gemm(
    const __half* __restrict__ A, const __half* __restrict__ We1,
    const float* __restrict__ be1, const float* __restrict__ wsel,
    const __half* __restrict__ We2, float* __restrict__ part)
{
    extern __shared__ char smem[];
    constexpr int BN = 256, K = 512;
    constexpr int RSB = BN * 2 + 16;
    constexpr int ASZ = 128 * RSA;
    constexpr int STG = ASZ + 32 * RSB;
    constexpr int CPR = BN / 8;
    constexpr int NF  = 8;
    constexpr int GBUF = 0;
    constexpr int W2S  = 128 * RSG;
    float* sbias = (float*)(smem + 3 * STG);

    const int tid = threadIdx.x, warp = tid >> 5, lane = tid & 31;
    const int rA = (warp >> 2) * 64, cB = (warp & 3) * 64;
    const int lg = lane >> 2, lt = lane & 3;
    const int m0 = blockIdx.y * 128;
    const int e  = blockIdx.x;

    const __half* Bp = We1 + (size_t)e * K * 256;

    for (int i = tid; i < BN; i += 256) sbias[i] = be1[e * 256 + i];

    const uint32_t smb = smem_u32(smem);
    const int li = lane & 7, ls = lane >> 3;
    const uint32_t aOff = (uint32_t)(rA + li + 8 * (ls & 1)) * RSA + (ls >> 1) * 16;
    const uint32_t bOff = ASZ + (uint32_t)(li + 8 * (ls & 1)) * RSB
                        + (uint32_t)(cB + 8 * (ls >> 1)) * 2;

    float acc[4][NF][4];
#pragma unroll
    for (int i = 0; i < 4; i++)
#pragma unroll
        for (int j = 0; j < NF; j++)
#pragma unroll
            for (int k = 0; k < 4; k++) acc[i][j][k] = 0.f;

    const int NT = K >> 5;

#define LOAD_STAGE(t, bufi)                                                    \
    {                                                                          \
        const uint32_t base = smb + (bufi) * STG;                              \
        const int k0 = (t) * 32;                                               \
        _Pragma("unroll")                                                      \
        for (int j = 0; j < 2; j++) {                                          \
            int i = tid + 256 * j;                                             \
            int r = i >> 2, q = i & 3;                                         \
            CP_ASYNC16(base + r * RSA + q * 16,                                \
                       A + (size_t)(m0 + r) * K + k0 + q * 8);                 \
        }                                                                      \
        _Pragma("unroll")                                                      \
        for (int j = 0; j < 4; j++) {                                          \
            int i = tid + 256 * j;                                             \
            int krow = i / CPR, c16 = i % CPR;                                 \
            CP_ASYNC16(base + ASZ + krow * RSB + c16 * 16,                     \
                       Bp + (size_t)(k0 + krow) * 256 + c16 * 8);              \
        }                                                                      \
        CP_COMMIT();                                                           \
    }

    LOAD_STAGE(0, 0);
    LOAD_STAGE(1, 1);

    int buf = 0, nbuf = 2;
    for (int t = 0; t < NT; t++) {
        if (t + 1 < NT) { CP_WAIT1(); } else { CP_WAIT0(); }
        __syncthreads();
        if (t + 2 < NT) { LOAD_STAGE(t + 2, nbuf); }

        const uint32_t base = smb + buf * STG;
        uint32_t a[2][4][4];
        uint32_t b[2][4][4];
#pragma unroll
        for (int h = 0; h < 2; h++) {
#pragma unroll
            for (int mf = 0; mf < 4; mf++)
                LDSM_X4(a[h][mf], base + aOff + mf * (16 * RSA) + h * 32);
#pragma unroll
            for (int nfp = 0; nfp < 4; nfp++)
                LDSM_X4_T(b[h][nfp], base + bOff + nfp * 32 + h * (16 * RSB));
        }
#pragma unroll
        for (int h = 0; h < 2; h++)
#pragma unroll
            for (int mf = 0; mf < 4; mf++)
#pragma unroll
                for (int nf = 0; nf < NF; nf++)
                    mma_f16(acc[mf][nf], a[h][mf],
                            b[h][nf >> 1][(nf & 1) * 2], b[h][nf >> 1][(nf & 1) * 2 + 1]);
        buf = (buf == 2) ? 0 : buf + 1;
        nbuf = (nbuf == 2) ? 0 : nbuf + 1;
    }
#undef LOAD_STAGE

    __syncthreads();   // epilogue overlays stage buffers; all compute must finish

    // ---- epilogue 1: bias + relu + w-scale, pack g into smem ----
#pragma unroll
    for (int mf = 0; mf < 4; mf++) {
        int row = m0 + rA + mf * 16 + lg;
        int lr0 = rA + mf * 16 + lg;
        float ws0 = wsel[(size_t)row * 16 + e];
        float ws1 = wsel[(size_t)(row + 8) * 16 + e];
#pragma unroll
        for (int nf = 0; nf < NF; nf++) {
            int cl = cB + nf * 8 + lt * 2;
            float b0 = sbias[cl], b1 = sbias[cl + 1];
            float v0 = fmaxf(acc[mf][nf][0] + b0, 0.f) * ws0;
            float v1 = fmaxf(acc[mf][nf][1] + b1, 0.f) * ws0;
            float v2 = fmaxf(acc[mf][nf][2] + b0, 0.f) * ws1;
            float v3 = fmaxf(acc[mf][nf][3] + b1, 0.f) * ws1;
            *(uint32_t*)(smem + GBUF + lr0 * RSG + cl * 2)       = packh2(v0, v1);
            *(uint32_t*)(smem + GBUF + (lr0 + 8) * RSG + cl * 2) = packh2(v2, v3);
        }
    }

    // ---- load We2[e] (256x32 half) into smem, stride 80 ----
#pragma unroll
    for (int j = 0; j < 4; j++) {
        int i = tid + 256 * j;
        int hrow = i >> 2, q = i & 3;
        uint4 u = *(const uint4*)(We2 + ((size_t)e * 256 + hrow) * 32 + q * 8);
        *(uint4*)(smem + W2S + hrow * RSA + q * 16) = u;
    }
    __syncthreads();

    // ---- mini-GEMM: part_tile = g(128x256) @ We2s(256x32) ----
    {
        const uint32_t aAddr2 = smb + GBUF
            + (uint32_t)(warp * 16 + li + 8 * (ls & 1)) * RSG + (ls >> 1) * 16;
        const uint32_t bAddr2 = smb + W2S
            + (uint32_t)(li + 8 * (ls & 1)) * RSA + (uint32_t)(8 * (ls >> 1)) * 2;

        float acc2[4][4];
#pragma unroll
        for (int nf = 0; nf < 4; nf++)
#pragma unroll
            for (int k = 0; k < 4; k++) acc2[nf][k] = 0.f;

#pragma unroll
        for (int ks = 0; ks < 16; ks++) {
            uint32_t a[4];
            LDSM_X4(a, aAddr2 + ks * 32);
            uint32_t b[2][4];
#pragma unroll
            for (int nfp = 0; nfp < 2; nfp++)
                LDSM_X4_T(b[nfp], bAddr2 + nfp * 32 + ks * (16 * RSA));
#pragma unroll
            for (int nf = 0; nf < 4; nf++)
                mma_f16(acc2[nf], a, b[nf >> 1][(nf & 1) * 2], b[nf >> 1][(nf & 1) * 2 + 1]);
        }

        float* P = part + (size_t)e * ((size_t)BATCH * 32);
        int row = m0 + warp * 16 + lg;
#pragma unroll
        for (int nf = 0; nf < 4; nf++) {
            int col = nf * 8 + lt * 2;
            *(float2*)(P + (size_t)row * 32 + col)       = make_float2(acc2[nf][0], acc2[nf][1]);
            *(float2*)(P + (size_t)(row + 8) * 32 + col) = make_float2(acc2[nf][2], acc2[nf][3]);
        }
    }
}

// ---------------- selector logits + softmax + fused row bias ----------------
__global__ __launch_bounds__(256) void selector_kernel(
    const __half* __restrict__ s1, const float* __restrict__ Ws2,
    const float* __restrict__ bs2, const float* __restrict__ be2,
    float* __restrict__ wout, float* __restrict__ rbout)
{
    __shared__ float Wsm[128 * 16];
    __shared__ float bsm[16];
    __shared__ float be2s[16 * 32];
    const int tid = threadIdx.x;
    for (int i = tid; i < 2048; i += 256) Wsm[i] = Ws2[i];
    for (int i = tid; i < 512; i += 256) be2s[i] = be2[i];
    if (tid < 16) bsm[tid] = bs2[tid];
    __syncthreads();

    const int warp = tid >> 5, lane = tid & 31;
    const int row = blockIdx.x * 8 + warp;

    float v[4];
#pragma unroll
    for (int j = 0; j < 4; j++)
        v[j] = __half2float(s1[(size_t)row * 128 + j * 32 + lane]);

    float mylog = -1e30f;
#pragma unroll
    for (int e = 0; e < 16; e++) {
        float p = 0.f;
#pragma unroll
        for (int j = 0; j < 4; j++) p += v[j] * Wsm[(j * 32 + lane) * 16 + e];
#pragma unroll
        for (int off = 16; off >= 1; off >>= 1)
            p += __shfl_xor_sync(0xffffffffu, p, off);
        if (lane == e) mylog = p + bsm[e];
    }
    float m = mylog;
#pragma unroll
    for (int off = 8; off >= 1; off >>= 1)
        m = fmaxf(m, __shfl_xor_sync(0xffffffffu, m, off, 16));
    float ex = __expf(mylog - m);
    float s = ex;
#pragma unroll
    for (int off = 8; off >= 1; off >>= 1)
        s += __shfl_xor_sync(0xffffffffu, s, off, 16);
    float wv = ex / s;
    if (lane < 16) wout[(size_t)row * 16 + lane] = wv;

    float rbv = 0.f;
#pragma unroll
    for (int e = 0; e < 16; e++) {
        float we = __shfl_sync(0xffffffffu, wv, e);
        rbv += we * be2s[e * 32 + lane];
    }
    rbout[(size_t)row * 32 + lane] = rbv;
}

// ---------------- 16-way partial reduce + row-bias --------------------------
__global__ __launch_bounds__(256) void reduce_final(
    const float* __restrict__ part, const float* __restrict__ rb,
    float* __restrict__ out)
{
    size_t idx = (size_t)blockIdx.x * 256 + threadIdx.x;
    const size_t S = (size_t)BATCH * 32 / 4;
    const float4* p4 = (const float4*)part;
    float4 r = ((const float4*)rb)[idx];
#pragma unroll
    for (int s = 0; s < 16; s++) {
        float4 p = p4[s * S + idx];
        r.x += p.x; r.y += p.y; r.z += p.z; r.w += p.w;
    }
    ((float4*)out)[idx] = r;
}

// ---------------- launch -----------------------------------------------------
extern "C" void kernel_launch(void* const* d_in, const int* in_sizes, int n_in,
                              void* d_out, int out_size)
{
    const float* obs = (const float*)d_in[0];
    const float* Wb0 = (const float*)d_in[1];  const float* bb0 = (const float*)d_in[2];
    const float* Wb1 = (const float*)d_in[3];  const float* bb1 = (const float*)d_in[4];
    const float* Wb2 = (const float*)d_in[5];  const float* bb2 = (const float*)d_in[6];
    const float* We1 = (const float*)d_in[7];  const float* be1 = (const float*)d_in[8];
    const float* We2 = (const float*)d_in[9];  const float* be2 = (const float*)d_in[10];
    const float* Ws0 = (const float*)d_in[11]; const float* bs0 = (const float*)d_in[12];
    const float* Ws1 = (const float*)d_in[13]; const float* bs1 = (const float*)d_in[14];
    const float* Ws2 = (const float*)d_in[15]; const float* bs2 = (const float*)d_in[16];
    float* out = (float*)d_out;

    __half *obsh, *h0s0, *h1, *h2, *s1;
    __half *W0cat, *Wb1h, *Wb2h, *Ws1h, *We1h, *We2h;
    float *b0cat, *w, *rb, *part;
    cudaGetSymbolAddress((void**)&obsh, g_obsh);
    cudaGetSymbolAddress((void**)&h0s0, g_h0s0);
    cudaGetSymbolAddress((void**)&h1, g_h1);
    cudaGetSymbolAddress((void**)&h2, g_h2);
    cudaGetSymbolAddress((void**)&s1, g_s1);
    cudaGetSymbolAddress((void**)&w,  g_w);
    cudaGetSymbolAddress((void**)&rb, g_rb);
    cudaGetSymbolAddress((void**)&part, g_part);
    cudaGetSymbolAddress((void**)&W0cat, g_W0cat);
    cudaGetSymbolAddress((void**)&b0cat, g_b0cat);
    cudaGetSymbolAddress((void**)&Wb1h, g_Wb1h);
    cudaGetSymbolAddress((void**)&Wb2h, g_Wb2h);
    cudaGetSymbolAddress((void**)&Ws1h, g_Ws1h);
    cudaGetSymbolAddress((void**)&We1h, g_We1h);
    cudaGetSymbolAddress((void**)&We2h, g_We2h);

    constexpr int RSB256 = 256 * 2 + 16, RSB128 = 128 * 2 + 16;
    constexpr int STG256 = 128 * RSA + 32 * RSB256;          // 27136
    constexpr int STG128 = 128 * RSA + 32 * RSB128;          // 18944
    constexpr int SM256 = 3 * STG256 + 256 * 4;              // 82432
    constexpr int SM128 = 3 * STG128 + 128 * 4;              // 57344
    cudaFuncSetAttribute((const void*)tc_gemm<256, true>,
                         cudaFuncAttributeMaxDynamicSharedMemorySize, SM256);
    cudaFuncSetAttribute((const void*)tc_gemm<128, true>,
                         cudaFuncAttributeMaxDynamicSharedMemorySize, SM128);
    cudaFuncSetAttribute((const void*)expert_gemm,
                         cudaFuncAttributeMaxDynamicSharedMemorySize, 90112);

    auto cvt = [](const float* s, __half* d, size_t n) {
        size_t n8 = n / 8;
        f2h_kernel<<<(unsigned)((n8 + 255) / 256), 256>>>(s, d, n8);
    };
    cvt(obs, obsh, (size_t)BATCH * 512);
    cat_kernel<<<(512 * 1280 + 255) / 256, 256>>>(Wb0, Ws0, bb0, bs0, W0cat, b0cat);
    cvt(Wb1, Wb1h, 1024 * 1024);
    cvt(Wb2, Wb2h, 1024 * 512);
    cvt(Ws1, Ws1h, 256 * 128);
    cvt(We1, We1h, 16 * 512 * 256);
    cvt(We2, We2h, 4096 * 32);

    const int MB = BATCH / 128;   // 512

    // fused backbone-L0 + selector-S0: [B,512] @ [512,1280] -> [h0 | s0]
    tc_gemm<256, true><<<dim3(5, MB), 256, SM256>>>(obsh, W0cat, b0cat, h0s0, 512, 1280, 512);

    // selector chain
    tc_gemm<128, true><<<dim3(1, MB), 256, SM128>>>(h0s0 + 1024, Ws1h, bs1, s1, 256, 128, 1280);
    selector_kernel<<<BATCH / 8, 256>>>(s1, Ws2, bs2, be2, w, rb);

    // backbone
    tc_gemm<256, true><<<dim3(4, MB), 256, SM256>>>(h0s0, Wb1h, bb1, h1, 1024, 1024, 1280);
    tc_gemm<256, true><<<dim3(2, MB), 256, SM256>>>(h1, Wb2h, bb2, h2, 1024, 512, 1024);

    // fused experts
    expert_gemm<<<dim3(16, MB), 256, 90112>>>(h2, We1h, be1, w, We2h, part);

    // final reduce
    reduce_final<<<(BATCH * 32 / 4) / 256, 256>>>(part, rb, out);
}

// round 10
// speedup vs baseline: 2.8408x; 1.1505x over previous
#include <cuda_runtime.h>
#include <cuda_fp16.h>
#include <cstdint>

#define BATCH 65536
#define RSA 80     // A smem row: 32 halfs (64B) + 16B pad
#define RSG 528    // g smem row: 256 halfs (512B) + 16B pad

// ---------------- scratch (device globals; no allocation allowed) ----------
__device__ __half g_obsh[(size_t)BATCH * 512];
__device__ __half g_h0s0[(size_t)BATCH * 1280];   // [h0 | s0] packed
__device__ __half g_h1[(size_t)BATCH * 1024];
__device__ __half g_h2[(size_t)BATCH * 512];
__device__ __half g_s1[(size_t)BATCH * 128];
__device__ float  g_w [(size_t)BATCH * 16];
__device__ float  g_rb[(size_t)BATCH * 32];
__device__ float  g_part[(size_t)16 * BATCH * 32];
// fp16 weights (converted once per replay; deterministic)
__device__ __half g_W0cat[512 * 1280];            // [Wb0 | Ws0]
__device__ float  g_b0cat[1280];
__device__ __half g_Wb1h[1024 * 1024];
__device__ __half g_Wb2h[1024 * 512];
__device__ __half g_Ws1h[256 * 128];
__device__ __half g_We1h[16 * 512 * 256];
__device__ __half g_We2h[4096 * 32];

// ---------------- helpers ---------------------------------------------------
__device__ __forceinline__ uint32_t smem_u32(const void* p) {
    uint32_t a;
    asm("{ .reg .u64 t; cvta.to.shared.u64 t, %1; cvt.u32.u64 %0, t; }" : "=r"(a) : "l"(p));
    return a;
}
__device__ __forceinline__ void mma_f16(float* d, const uint32_t* a, uint32_t b0, uint32_t b1) {
    asm volatile(
        "mma.sync.aligned.m16n8k16.row.col.f32.f16.f16.f32 "
        "{%0,%1,%2,%3}, {%4,%5,%6,%7}, {%8,%9}, {%0,%1,%2,%3};\n"
        : "+f"(d[0]), "+f"(d[1]), "+f"(d[2]), "+f"(d[3])
        : "r"(a[0]), "r"(a[1]), "r"(a[2]), "r"(a[3]), "r"(b0), "r"(b1));
}
#define LDSM_X4(r, addr) \
    asm volatile("ldmatrix.sync.aligned.m8n8.x4.shared.b16 {%0,%1,%2,%3}, [%4];" \
        : "=r"((r)[0]), "=r"((r)[1]), "=r"((r)[2]), "=r"((r)[3]) : "r"(addr))
#define LDSM_X4_T(r, addr) \
    asm volatile("ldmatrix.sync.aligned.m8n8.x4.trans.shared.b16 {%0,%1,%2,%3}, [%4];" \
        : "=r"((r)[0]), "=r"((r)[1]), "=r"((r)[2]), "=r"((r)[3]) : "r"(addr))
#define CP_ASYNC16(dst, src) \
    asm volatile("cp.async.cg.shared.global [%0], [%1], 16;\n" :: "r"(dst), "l"(src))
#define CP_COMMIT() asm volatile("cp.async.commit_group;\n" ::: "memory")
#define CP_WAIT1()  asm volatile("cp.async.wait_group 1;\n" ::: "memory")
#define CP_WAIT0()  asm volatile("cp.async.wait_group 0;\n" ::: "memory")

__device__ __forceinline__ uint32_t packh2(float lo, float hi) {
    __half2 h = __floats2half2_rn(lo, hi);
    return *(uint32_t*)&h;
}

// ---------------- fp32 -> fp16 conversion (8 elems/thread) ------------------
__global__ __launch_bounds__(256) void f2h_kernel(
    const float* __restrict__ src, __half* __restrict__ dst, size_t n8)
{
    size_t i = (size_t)blockIdx.x * 256 + threadIdx.x;
    if (i >= n8) return;
    float4 a = ((const float4*)src)[2 * i];
    float4 b = ((const float4*)src)[2 * i + 1];
    uint4 u;
    u.x = packh2(a.x, a.y); u.y = packh2(a.z, a.w);
    u.z = packh2(b.x, b.y); u.w = packh2(b.z, b.w);
    ((uint4*)dst)[i] = u;
}

// ---------------- concat-convert: W0cat = [Wb0 | Ws0] fp16, b0cat -----------
__global__ __launch_bounds__(256) void cat_kernel(
    const float* __restrict__ Wb0, const float* __restrict__ Ws0,
    const float* __restrict__ bb0, const float* __restrict__ bs0,
    __half* __restrict__ Wcat, float* __restrict__ bcat)
{
    size_t i = (size_t)blockIdx.x * 256 + threadIdx.x;
    if (i < (size_t)512 * 1280) {
        int k = (int)(i / 1280), c = (int)(i % 1280);
        float v = (c < 1024) ? Wb0[(size_t)k * 1024 + c] : Ws0[(size_t)k * 256 + (c - 1024)];
        Wcat[i] = __float2half_rn(v);
    }
    if (i < 1280) bcat[i] = (i < 1024) ? bb0[i] : bs0[i - 1024];
}

// ---------------- generic GEMM: C(half) = act(A @ B + bias) -----------------
// 128 x 128 block, 128 thr, 4 warps (2x2), warp tile 64x64.
// 3-stage cp.async pipeline, hoisted ldmatrix, 2 CTAs/SM for overlap.
template<bool RELU>
__global__ __launch_bounds__(128, 2) void tc_gemm(
    const __half* __restrict__ A, const __half* __restrict__ B,
    const float* __restrict__ bias, __half* __restrict__ C,
    int K, int N, int lda)
{
    extern __shared__ char smem[];
    constexpr int BN  = 128;
    constexpr int RSB = BN * 2 + 16;           // 272
    constexpr int ASZ = 128 * RSA;             // 10240
    constexpr int STG = ASZ + 32 * RSB;        // 18944
    constexpr int NF  = 8;                     // 8 n-frags of 8 cols (64 cols/warp)
    float* sbias = (float*)(smem + 3 * STG);

    const int tid = threadIdx.x, warp = tid >> 5, lane = tid & 31;
    const int rA = (warp >> 1) * 64, cB = (warp & 1) * 64;
    const int lg = lane >> 2, lt = lane & 3;
    const int m0 = blockIdx.y * 128, n0 = blockIdx.x * BN;

    const __half* Bp = B + n0;

    if (tid < BN) sbias[tid] = bias[n0 + tid];

    const uint32_t smb = smem_u32(smem);
    const int li = lane & 7, ls = lane >> 3;
    const uint32_t aOff = (uint32_t)(rA + li + 8 * (ls & 1)) * RSA + (ls >> 1) * 16;
    const uint32_t bOff = ASZ + (uint32_t)(li + 8 * (ls & 1)) * RSB
                        + (uint32_t)(cB + 8 * (ls >> 1)) * 2;

    float acc[4][NF][4];
#pragma unroll
    for (int i = 0; i < 4; i++)
#pragma unroll
        for (int j = 0; j < NF; j++)
#pragma unroll
            for (int k = 0; k < 4; k++) acc[i][j][k] = 0.f;

    const int NT = K >> 5;

#define LOAD_STAGE(t, buf)                                                     \
    {                                                                          \
        const uint32_t base = smb + (buf) * STG;                               \
        const int k0 = (t) * 32;                                               \
        _Pragma("unroll")                                                      \
        for (int j = 0; j < 4; j++) {                                          \
            int i = tid + 128 * j;                                             \
            int r = i >> 2, q = i & 3;                                         \
            CP_ASYNC16(base + r * RSA + q * 16,                                \
                       A + (size_t)(m0 + r) * lda + k0 + q * 8);               \
        }                                                                      \
        _Pragma("unroll")                                                      \
        for (int j = 0; j < 4; j++) {                                          \
            int i = tid + 128 * j;                                             \
            int krow = i >> 4, c16 = i & 15;                                   \
            CP_ASYNC16(base + ASZ + krow * RSB + c16 * 16,                     \
                       Bp + (size_t)(k0 + krow) * N + c16 * 8);                \
        }                                                                      \
        CP_COMMIT();                                                           \
    }

    LOAD_STAGE(0, 0);
    LOAD_STAGE(1, 1);

    int buf = 0, nbuf = 2;
    for (int t = 0; t < NT; t++) {
        if (t + 1 < NT) { CP_WAIT1(); } else { CP_WAIT0(); }
        __syncthreads();
        if (t + 2 < NT) { LOAD_STAGE(t + 2, nbuf); }

        const uint32_t base = smb + buf * STG;
        uint32_t a[2][4][4];
        uint32_t b[2][NF / 2][4];
#pragma unroll
        for (int h = 0; h < 2; h++) {
#pragma unroll
            for (int mf = 0; mf < 4; mf++)
                LDSM_X4(a[h][mf], base + aOff + mf * (16 * RSA) + h * 32);
#pragma unroll
            for (int nfp = 0; nfp < NF / 2; nfp++)
                LDSM_X4_T(b[h][nfp], base + bOff + nfp * 32 + h * (16 * RSB));
        }
#pragma unroll
        for (int h = 0; h < 2; h++)
#pragma unroll
            for (int mf = 0; mf < 4; mf++)
#pragma unroll
                for (int nf = 0; nf < NF; nf++)
                    mma_f16(acc[mf][nf], a[h][mf],
                            b[h][nf >> 1][(nf & 1) * 2], b[h][nf >> 1][(nf & 1) * 2 + 1]);
        // no trailing barrier: 3-stage ring, next overwrite of this buffer is
        // ordered by the NEXT iteration's top-of-loop barrier.
        buf = (buf == 2) ? 0 : buf + 1;
        nbuf = (nbuf == 2) ? 0 : nbuf + 1;
    }
#undef LOAD_STAGE

#pragma unroll
    for (int mf = 0; mf < 4; mf++) {
        int row = m0 + rA + mf * 16 + lg;
#pragma unroll
        for (int nf = 0; nf < NF; nf++) {
            int cl = cB + nf * 8 + lt * 2;
            int col = n0 + cl;
            float b0 = sbias[cl], b1 = sbias[cl + 1];
            float v0 = acc[mf][nf][0] + b0, v1 = acc[mf][nf][1] + b1;
            float v2 = acc[mf][nf][2] + b0, v3 = acc[mf][nf][3] + b1;
            if (RELU) {
                v0 = fmaxf(v0, 0.f); v1 = fmaxf(v1, 0.f);
                v2 = fmaxf(v2, 0.f); v3 = fmaxf(v3, 0.f);
            }
            *(uint32_t*)(C + (size_t)row * N + col)       = packh2(v0, v1);
            *(uint32_t*)(C + (size_t)(row + 8) * N + col) = packh2(v2, v3);
        }
    }
}

// ---------------- fused expert kernel (unchanged structure) -----------------
__global__ __launch_bounds__(256, 1) void expert_gemm(
    const __half* __restrict__ A, const __half* __restrict__ We1,
    const float* __restrict__ be1, const float* __restrict__ wsel,
    const __half* __restrict__ We2, float* __restrict__ part)
{
    extern __shared__ char smem[];
    constexpr int BN = 256, K = 512;
    constexpr int RSB = BN * 2 + 16;
    constexpr int ASZ = 128 * RSA;
    constexpr int STG = ASZ + 32 * RSB;
    constexpr int CPR = BN / 8;
    constexpr int NF  = 8;
    constexpr int GBUF = 0;
    constexpr int W2S  = 128 * RSG;
    float* sbias = (float*)(smem + 3 * STG);

    const int tid = threadIdx.x, warp = tid >> 5, lane = tid & 31;
    const int rA = (warp >> 2) * 64, cB = (warp & 3) * 64;
    const int lg = lane >> 2, lt = lane & 3;
    const int m0 = blockIdx.y * 128;
    const int e  = blockIdx.x;

    const __half* Bp = We1 + (size_t)e * K * 256;

    for (int i = tid; i < BN; i += 256) sbias[i] = be1[e * 256 + i];

    const uint32_t smb = smem_u32(smem);
    const int li = lane & 7, ls = lane >> 3;
    const uint32_t aOff = (uint32_t)(rA + li + 8 * (ls & 1)) * RSA + (ls >> 1) * 16;
    const uint32_t bOff = ASZ + (uint32_t)(li + 8 * (ls & 1)) * RSB
                        + (uint32_t)(cB + 8 * (ls >> 1)) * 2;

    float acc[4][NF][4];
#pragma unroll
    for (int i = 0; i < 4; i++)
#pragma unroll
        for (int j = 0; j < NF; j++)
#pragma unroll
            for (int k = 0; k < 4; k++) acc[i][j][k] = 0.f;

    const int NT = K >> 5;

#define LOAD_STAGE(t, bufi)                                                    \
    {                                                                          \
        const uint32_t base = smb + (bufi) * STG;                              \
        const int k0 = (t) * 32;                                               \
        _Pragma("unroll")                                                      \
        for (int j = 0; j < 2; j++) {                                          \
            int i = tid + 256 * j;                                             \
            int r = i >> 2, q = i & 3;                                         \
            CP_ASYNC16(base + r * RSA + q * 16,                                \
                       A + (size_t)(m0 + r) * K + k0 + q * 8);                 \
        }                                                                      \
        _Pragma("unroll")                                                      \
        for (int j = 0; j < 4; j++) {                                          \
            int i = tid + 256 * j;                                             \
            int krow = i / CPR, c16 = i % CPR;                                 \
            CP_ASYNC16(base + ASZ + krow * RSB + c16 * 16,                     \
                       Bp + (size_t)(k0 + krow) * 256 + c16 * 8);              \
        }                                                                      \
        CP_COMMIT();                                                           \
    }

    LOAD_STAGE(0, 0);
    LOAD_STAGE(1, 1);

    int buf = 0, nbuf = 2;
    for (int t = 0; t < NT; t++) {
        if (t + 1 < NT) { CP_WAIT1(); } else { CP_WAIT0(); }
        __syncthreads();
        if (t + 2 < NT) { LOAD_STAGE(t + 2, nbuf); }

        const uint32_t base = smb + buf * STG;
        uint32_t a[2][4][4];
        uint32_t b[2][4][4];
#pragma unroll
        for (int h = 0; h < 2; h++) {
#pragma unroll
            for (int mf = 0; mf < 4; mf++)
                LDSM_X4(a[h][mf], base + aOff + mf * (16 * RSA) + h * 32);
#pragma unroll
            for (int nfp = 0; nfp < 4; nfp++)
                LDSM_X4_T(b[h][nfp], base + bOff + nfp * 32 + h * (16 * RSB));
        }
#pragma unroll
        for (int h = 0; h < 2; h++)
#pragma unroll
            for (int mf = 0; mf < 4; mf++)
#pragma unroll
                for (int nf = 0; nf < NF; nf++)
                    mma_f16(acc[mf][nf], a[h][mf],
                            b[h][nf >> 1][(nf & 1) * 2], b[h][nf >> 1][(nf & 1) * 2 + 1]);
        buf = (buf == 2) ? 0 : buf + 1;
        nbuf = (nbuf == 2) ? 0 : nbuf + 1;
    }
#undef LOAD_STAGE

    __syncthreads();   // epilogue overlays stage buffers

    // ---- epilogue 1: bias + relu + w-scale, pack g into smem ----
#pragma unroll
    for (int mf = 0; mf < 4; mf++) {
        int row = m0 + rA + mf * 16 + lg;
        int lr0 = rA + mf * 16 + lg;
        float ws0 = wsel[(size_t)row * 16 + e];
        float ws1 = wsel[(size_t)(row + 8) * 16 + e];
#pragma unroll
        for (int nf = 0; nf < NF; nf++) {
            int cl = cB + nf * 8 + lt * 2;
            float b0 = sbias[cl], b1 = sbias[cl + 1];
            float v0 = fmaxf(acc[mf][nf][0] + b0, 0.f) * ws0;
            float v1 = fmaxf(acc[mf][nf][1] + b1, 0.f) * ws0;
            float v2 = fmaxf(acc[mf][nf][2] + b0, 0.f) * ws1;
            float v3 = fmaxf(acc[mf][nf][3] + b1, 0.f) * ws1;
            *(uint32_t*)(smem + GBUF + lr0 * RSG + cl * 2)       = packh2(v0, v1);
            *(uint32_t*)(smem + GBUF + (lr0 + 8) * RSG + cl * 2) = packh2(v2, v3);
        }
    }

    // ---- load We2[e] (256x32 half) into smem ----
#pragma unroll
    for (int j = 0; j < 4; j++) {
        int i = tid + 256 * j;
        int hrow = i >> 2, q = i & 3;
        uint4 u = *(const uint4*)(We2 + ((size_t)e * 256 + hrow) * 32 + q * 8);
        *(uint4*)(smem + W2S + hrow * RSA + q * 16) = u;
    }
    __syncthreads();

    // ---- mini-GEMM: part_tile = g(128x256) @ We2s(256x32) ----
    {
        const uint32_t aAddr2 = smb + GBUF
            + (uint32_t)(warp * 16 + li + 8 * (ls & 1)) * RSG + (ls >> 1) * 16;
        const uint32_t bAddr2 = smb + W2S
            + (uint32_t)(li + 8 * (ls & 1)) * RSA + (uint32_t)(8 * (ls >> 1)) * 2;

        float acc2[4][4];
#pragma unroll
        for (int nf = 0; nf < 4; nf++)
#pragma unroll
            for (int k = 0; k < 4; k++) acc2[nf][k] = 0.f;

#pragma unroll
        for (int ks = 0; ks < 16; ks++) {
            uint32_t a[4];
            LDSM_X4(a, aAddr2 + ks * 32);
            uint32_t b[2][4];
#pragma unroll
            for (int nfp = 0; nfp < 2; nfp++)
                LDSM_X4_T(b[nfp], bAddr2 + nfp * 32 + ks * (16 * RSA));
#pragma unroll
            for (int nf = 0; nf < 4; nf++)
                mma_f16(acc2[nf], a, b[nf >> 1][(nf & 1) * 2], b[nf >> 1][(nf & 1) * 2 + 1]);
        }

        float* P = part + (size_t)e * ((size_t)BATCH * 32);
        int row = m0 + warp * 16 + lg;
#pragma unroll
        for (int nf = 0; nf < 4; nf++) {
            int col = nf * 8 + lt * 2;
            *(float2*)(P + (size_t)row * 32 + col)       = make_float2(acc2[nf][0], acc2[nf][1]);
            *(float2*)(P + (size_t)(row + 8) * 32 + col) = make_float2(acc2[nf][2], acc2[nf][3]);
        }
    }
}

// ---------------- selector logits + softmax + fused row bias ----------------
__global__ __launch_bounds__(256) void selector_kernel(
    const __half* __restrict__ s1, const float* __restrict__ Ws2,
    const float* __restrict__ bs2, const float* __restrict__ be2,
    float* __restrict__ wout, float* __restrict__ rbout)
{
    __shared__ float Wsm[128 * 16];
    __shared__ float bsm[16];
    __shared__ float be2s[16 * 32];
    const int tid = threadIdx.x;
    for (int i = tid; i < 2048; i += 256) Wsm[i] = Ws2[i];
    for (int i = tid; i < 512; i += 256) be2s[i] = be2[i];
    if (tid < 16) bsm[tid] = bs2[tid];
    __syncthreads();

    const int warp = tid >> 5, lane = tid & 31;
    const int row = blockIdx.x * 8 + warp;

    float v[4];
#pragma unroll
    for (int j = 0; j < 4; j++)
        v[j] = __half2float(s1[(size_t)row * 128 + j * 32 + lane]);

    float mylog = -1e30f;
#pragma unroll
    for (int e = 0; e < 16; e++) {
        float p = 0.f;
#pragma unroll
        for (int j = 0; j < 4; j++) p += v[j] * Wsm[(j * 32 + lane) * 16 + e];
#pragma unroll
        for (int off = 16; off >= 1; off >>= 1)
            p += __shfl_xor_sync(0xffffffffu, p, off);
        if (lane == e) mylog = p + bsm[e];
    }
    float m = mylog;
#pragma unroll
    for (int off = 8; off >= 1; off >>= 1)
        m = fmaxf(m, __shfl_xor_sync(0xffffffffu, m, off, 16));
    float ex = __expf(mylog - m);
    float s = ex;
#pragma unroll
    for (int off = 8; off >= 1; off >>= 1)
        s += __shfl_xor_sync(0xffffffffu, s, off, 16);
    float wv = ex / s;
    if (lane < 16) wout[(size_t)row * 16 + lane] = wv;

    float rbv = 0.f;
#pragma unroll
    for (int e = 0; e < 16; e++) {
        float we = __shfl_sync(0xffffffffu, wv, e);
        rbv += we * be2s[e * 32 + lane];
    }
    rbout[(size_t)row * 32 + lane] = rbv;
}

// ---------------- 16-way partial reduce + row-bias --------------------------
__global__ __launch_bounds__(256) void reduce_final(
    const float* __restrict__ part, const float* __restrict__ rb,
    float* __restrict__ out)
{
    size_t idx = (size_t)blockIdx.x * 256 + threadIdx.x;
    const size_t S = (size_t)BATCH * 32 / 4;
    const float4* p4 = (const float4*)part;
    float4 r = ((const float4*)rb)[idx];
#pragma unroll
    for (int s = 0; s < 16; s++) {
        float4 p = p4[s * S + idx];
        r.x += p.x; r.y += p.y; r.z += p.z; r.w += p.w;
    }
    ((float4*)out)[idx] = r;
}

// ---------------- launch -----------------------------------------------------
extern "C" void kernel_launch(void* const* d_in, const int* in_sizes, int n_in,
                              void* d_out, int out_size)
{
    const float* obs = (const float*)d_in[0];
    const float* Wb0 = (const float*)d_in[1];  const float* bb0 = (const float*)d_in[2];
    const float* Wb1 = (const float*)d_in[3];  const float* bb1 = (const float*)d_in[4];
    const float* Wb2 = (const float*)d_in[5];  const float* bb2 = (const float*)d_in[6];
    const float* We1 = (const float*)d_in[7];  const float* be1 = (const float*)d_in[8];
    const float* We2 = (const float*)d_in[9];  const float* be2 = (const float*)d_in[10];
    const float* Ws0 = (const float*)d_in[11]; const float* bs0 = (const float*)d_in[12];
    const float* Ws1 = (const float*)d_in[13]; const float* bs1 = (const float*)d_in[14];
    const float* Ws2 = (const float*)d_in[15]; const float* bs2 = (const float*)d_in[16];
    float* out = (float*)d_out;

    __half *obsh, *h0s0, *h1, *h2, *s1;
    __half *W0cat, *Wb1h, *Wb2h, *Ws1h, *We1h, *We2h;
    float *b0cat, *w, *rb, *part;
    cudaGetSymbolAddress((void**)&obsh, g_obsh);
    cudaGetSymbolAddress((void**)&h0s0, g_h0s0);
    cudaGetSymbolAddress((void**)&h1, g_h1);
    cudaGetSymbolAddress((void**)&h2, g_h2);
    cudaGetSymbolAddress((void**)&s1, g_s1);
    cudaGetSymbolAddress((void**)&w,  g_w);
    cudaGetSymbolAddress((void**)&rb, g_rb);
    cudaGetSymbolAddress((void**)&part, g_part);
    cudaGetSymbolAddress((void**)&W0cat, g_W0cat);
    cudaGetSymbolAddress((void**)&b0cat, g_b0cat);
    cudaGetSymbolAddress((void**)&Wb1h, g_Wb1h);
    cudaGetSymbolAddress((void**)&Wb2h, g_Wb2h);
    cudaGetSymbolAddress((void**)&Ws1h, g_Ws1h);
    cudaGetSymbolAddress((void**)&We1h, g_We1h);
    cudaGetSymbolAddress((void**)&We2h, g_We2h);

    constexpr int STG = 128 * RSA + 32 * 272;               // 18944
    constexpr int SMG = 3 * STG + 512;                      // 57344 (2 CTAs/SM)
    cudaFuncSetAttribute((const void*)tc_gemm<true>,
                         cudaFuncAttributeMaxDynamicSharedMemorySize, SMG);
    cudaFuncSetAttribute((const void*)expert_gemm,
                         cudaFuncAttributeMaxDynamicSharedMemorySize, 90112);

    auto cvt = [](const float* s, __half* d, size_t n) {
        size_t n8 = n / 8;
        f2h_kernel<<<(unsigned)((n8 + 255) / 256), 256>>>(s, d, n8);
    };
    cvt(obs, obsh, (size_t)BATCH * 512);
    cat_kernel<<<(512 * 1280 + 255) / 256, 256>>>(Wb0, Ws0, bb0, bs0, W0cat, b0cat);
    cvt(Wb1, Wb1h, 1024 * 1024);
    cvt(Wb2, Wb2h, 1024 * 512);
    cvt(Ws1, Ws1h, 256 * 128);
    cvt(We1, We1h, 16 * 512 * 256);
    cvt(We2, We2h, 4096 * 32);

    const int MB = BATCH / 128;   // 512

    // fused backbone-L0 + selector-S0: [B,512] @ [512,1280] -> [h0 | s0]
    tc_gemm<true><<<dim3(10, MB), 128, SMG>>>(obsh, W0cat, b0cat, h0s0, 512, 1280, 512);

    // selector chain
    tc_gemm<true><<<dim3(1, MB), 128, SMG>>>(h0s0 + 1024, Ws1h, bs1, s1, 256, 128, 1280);
    selector_kernel<<<BATCH / 8, 256>>>(s1, Ws2, bs2, be2, w, rb);

    // backbone
    tc_gemm<true><<<dim3(8, MB), 128, SMG>>>(h0s0, Wb1h, bb1, h1, 1024, 1024, 1280);
    tc_gemm<true><<<dim3(4, MB), 128, SMG>>>(h1, Wb2h, bb2, h2, 1024, 512, 1024);

    // fused experts
    expert_gemm<<<dim3(16, MB), 256, 90112>>>(h2, We1h, be1, w, We2h, part);

    // final reduce
    reduce_final<<<(BATCH * 32 / 4) / 256, 256>>>(part, rb, out);
}